// round 15
// baseline (speedup 1.0000x reference)
#include <cuda_runtime.h>
#include <math.h>
#include <stdint.h>

#define NTH 512
#define NN  50
#define KA  15
#define KS  35
#define SAQ 16
#define SSQ 37
#define QLD 132   // q/k/v row stride (floats): bank-conflict-free attention

// ------------- transposed weight scratch (block-contiguous quad layout) -------------
#define OFF_AATTN 0
#define OFF_SATTN 131072
#define OFF_AW1   262144
#define OFF_SW1   393216
#define OFF_AW2   524288
#define OFF_SW2   655360
#define OFF_WK    786432
#define OFF_WV    851968
#define OFF_WQM   917504
#define OFF_DWQ   966656
#define OFF_DWO   999424
#define WT_TOTAL  1032192

__device__ float g_wt[WT_TOTAL];

// ---------------- shared memory layout (float offsets) ----------------
#define O_XSX  0
#define O_XSY  64
#define O_H    128        // 40x128 interleaved = 5120
#define O_SCR  5248       // 20480: q@0,k@5280,v@10560 (stride 132); FF1; d2
#define O_OB   25728      // 5120 (also holds attention output ao, interleaved)
#define O_EA   30848      // 2048
#define O_KB   32896      // 4096
#define O_VB   36992      // 2048
#define O_EQ   39040      // 384
#define O_HDEC 39424
#define O_Q2   39552
#define O_ODEC 39680
#define O_SCT  39808
#define O_LG   39936
#define O_TCX  39952
#define O_TCY  39992
#define O_MISC 40032
#define O_INT  40040      // ints
#define O_WBUF 40144      // 16384 floats (64KB): gemmF staging / gemmK & matvecK partials
#define SMEM_FLOATS 56528
#define SMEM_BYTES (SMEM_FLOATS * 4)

struct Params {
    const float* x; const int* start;
    const float *aEmbW, *aEmbB, *aAttnB, *aB1, *aB2, *aLn;
    const float *sEmbW, *sEmbB, *sAttnB, *sB1, *sB2, *sLn;
    const float *bK, *bV, *bqm, *dbq, *dbo;
    float* out;
};

// ---------------- cluster helpers ----------------
__device__ __forceinline__ uint32_t smaddr(const void* p){
    uint32_t a;
    asm("{ .reg .u64 t; cvta.to.shared.u64 t, %1; cvt.u32.u64 %0, t; }" : "=r"(a) : "l"(p));
    return a;
}
__device__ __forceinline__ void stPeer(const void* lp, float v, uint32_t prank){
    uint32_t l = smaddr(lp), r;
    asm("mapa.shared::cluster.u32 %0, %1, %2;" : "=r"(r) : "r"(l), "r"(prank));
    asm volatile("st.shared::cluster.f32 [%0], %1;" :: "r"(r), "f"(v) : "memory");
}
__device__ __forceinline__ void stPeer2(const void* lp, unsigned long long v, uint32_t prank){
    uint32_t l = smaddr(lp), r;
    asm("mapa.shared::cluster.u32 %0, %1, %2;" : "=r"(r) : "r"(l), "r"(prank));
    asm volatile("st.shared::cluster.b64 [%0], %1;" :: "r"(r), "l"(v) : "memory");
}
#define CLUSTER_SYNC() do { \
    asm volatile("barrier.cluster.arrive.aligned;" ::: "memory"); \
    asm volatile("barrier.cluster.wait.aligned;" ::: "memory"); } while(0)

// ---------------- merged weight-transpose prologue ----------------
struct TQJobs {
    const float* src[11];
    int dstOff[11], R[11], C[11], nmat[11];
};

__global__ void tq_all(TQJobs jb)
{
#pragma unroll 1
    for (int s = 0; s < 11; s++) {
        const int R = jb.R[s], C = jb.C[s];
        const int total = jb.nmat[s] * R * C;
        const float* __restrict__ src = jb.src[s];
        const int dstOff = jb.dstOff[s];
        for (int idx = blockIdx.x * blockDim.x + threadIdx.x; idx < total;
             idx += gridDim.x * blockDim.x) {
            const int m = idx / (R * C);
            const int rem = idx - m * R * C;
            const int r = rem / C;
            const int c = rem - r * C;
            g_wt[dstOff + m * R * C + (c >> 7) * (R * 128)
                 + ((r >> 2) << 9) + ((c & 127) << 2) + (r & 3)] = src[idx];
        }
    }
}

// ---------------- fused multi-block smem-staged packed-f32x2 GEMM ----------------
// PTOT local pairs distributed over 4 thread-groups as (q4+1)x r4, q4 x (4-r4).
template<int PTOT, int DIN, int NBLK, int TC, bool RELU, bool LINOUT, int PEERMASK>
__device__ __forceinline__ void gemmF(const float* __restrict__ in,
                                      const float* __restrict__ wt,
                                      const float* const* bias,
                                      float* const* outp,
                                      const int* obase,
                                      const int* ocols,
                                      float* __restrict__ wbuf,
                                      int pairBase, uint32_t prank)
{
    constexpr int T    = DIN / (4 * TC);
    constexpr int BUF4 = NBLK * TC * 128;
    constexpr int F4PT = BUF4 / NTH;
    constexpr int Q4   = PTOT / 4;
    constexpr int R4   = PTOT & 3;
    constexpr int PPG  = Q4 + (R4 ? 1 : 0);      // max pairs per group
    const int j = threadIdx.x & 127;
    const int g = threadIdx.x >> 7;
    const bool tail = (R4 > 0) && (g < R4);       // group has the extra pair
    const int gbase = g * Q4 + ((g < R4) ? g : R4);
    const float* inb = in + (pairBase + gbase) * 2 * DIN;
    const float4* wg4 = reinterpret_cast<const float4*>(wt);
    float4* wb4 = reinterpret_cast<float4*>(wbuf);

    float4 pre[F4PT];
#pragma unroll
    for (int s = 0; s < F4PT; s++) {
        const int idx = threadIdx.x + s * NTH;
        const int bk = idx / (TC * 128);
        const int rem = idx - bk * (TC * 128);
        pre[s] = __ldg(wg4 + bk * (DIN * 32) + rem);
    }
    unsigned long long acc[NBLK][PPG];
#pragma unroll
    for (int bk = 0; bk < NBLK; bk++)
#pragma unroll
        for (int p = 0; p < PPG; p++) acc[bk][p] = 0ull;

#pragma unroll 1
    for (int t = 0; t < T; t++) {
        float4* wb = wb4 + (t & 1) * BUF4;
#pragma unroll
        for (int s = 0; s < F4PT; s++) wb[threadIdx.x + s * NTH] = pre[s];
        __syncthreads();
        if (t + 1 < T) {
#pragma unroll
            for (int s = 0; s < F4PT; s++) {
                const int idx = threadIdx.x + s * NTH;
                const int bk = idx / (TC * 128);
                const int rem = idx - bk * (TC * 128);
                pre[s] = __ldg(wg4 + bk * (DIN * 32) + (t + 1) * (TC * 128) + rem);
            }
        }
#pragma unroll
        for (int ci = 0; ci < TC; ci++) {
            const int kk = t * TC + ci;
            ulonglong2 a01[PPG], a23[PPG];
#pragma unroll
            for (int p = 0; p < PPG; p++) {
                if (p < Q4 || tail) {
                    const ulonglong2* ip =
                        reinterpret_cast<const ulonglong2*>(inb + p * 2 * DIN + 8 * kk);
                    a01[p] = ip[0];
                    a23[p] = ip[1];
                }
            }
#pragma unroll
            for (int bk = 0; bk < NBLK; bk++) {
                const float4 w = wb[bk * (TC * 128) + ci * 128 + j];
                unsigned long long w0, w1, w2, w3;
                asm("mov.b64 %0,{%1,%1};" : "=l"(w0) : "f"(w.x));
                asm("mov.b64 %0,{%1,%1};" : "=l"(w1) : "f"(w.y));
                asm("mov.b64 %0,{%1,%1};" : "=l"(w2) : "f"(w.z));
                asm("mov.b64 %0,{%1,%1};" : "=l"(w3) : "f"(w.w));
#pragma unroll
                for (int p = 0; p < PPG; p++) {
                    if (p < Q4 || tail) {
                        asm("fma.rn.f32x2 %0, %1, %2, %0;" : "+l"(acc[bk][p]) : "l"(a01[p].x), "l"(w0));
                        asm("fma.rn.f32x2 %0, %1, %2, %0;" : "+l"(acc[bk][p]) : "l"(a01[p].y), "l"(w1));
                        asm("fma.rn.f32x2 %0, %1, %2, %0;" : "+l"(acc[bk][p]) : "l"(a23[p].x), "l"(w2));
                        asm("fma.rn.f32x2 %0, %1, %2, %0;" : "+l"(acc[bk][p]) : "l"(a23[p].y), "l"(w3));
                    }
                }
            }
        }
    }
#pragma unroll
    for (int bk = 0; bk < NBLK; bk++) {
        const float bb = __ldg(bias[bk] + j);
#pragma unroll
        for (int p = 0; p < PPG; p++) {
            if (p < Q4 || tail) {
                float lo, hi;
                asm("mov.b64 {%0,%1}, %2;" : "=f"(lo), "=f"(hi) : "l"(acc[bk][p]));
                lo += bb; hi += bb;
                if (RELU) { lo = fmaxf(lo, 0.f); hi = fmaxf(hi, 0.f); }
                const int pr = pairBase + gbase + p;
                if (LINOUT) {
                    float* o0 = outp[bk] + (2 * pr + 0) * ocols[bk] + obase[bk] + j;
                    float* o1 = outp[bk] + (2 * pr + 1) * ocols[bk] + obase[bk] + j;
                    *o0 = lo; *o1 = hi;
                    if (PEERMASK & (1 << bk)) { stPeer(o0, lo, prank); stPeer(o1, hi, prank); }
                } else {
                    *reinterpret_cast<float2*>(outp[bk] + pr * 2 * ocols[bk]
                                               + 2 * (obase[bk] + j)) = make_float2(lo, hi);
                }
            }
        }
    }
    __syncthreads();
}

// ---------------- K-split packed-f32x2 GEMM (direct-LDG weights) ----------------
template<int LP, int DIN, int NBLK, bool RELU, int PEERMASK>
__device__ __forceinline__ void gemmK(const float* __restrict__ in,
                                      const float* __restrict__ wt,
                                      const float* const* bias,
                                      float* const* outp,
                                      const int* obase,
                                      const int* ocols,
                                      float* __restrict__ wbuf,
                                      int pairBase, uint32_t prank)
{
    constexpr int NCH = DIN / 16;
    const int j  = threadIdx.x & 127;
    const int kg = threadIdx.x >> 7;
    const float* inb = in + pairBase * 2 * DIN;
    const float4* wq = reinterpret_cast<const float4*>(wt) + (kg * NCH) * 128 + j;

    unsigned long long acc[NBLK][LP];
#pragma unroll
    for (int bk = 0; bk < NBLK; bk++)
#pragma unroll
        for (int p = 0; p < LP; p++) acc[bk][p] = 0ull;

    float4 wc[NBLK], wn[NBLK];
#pragma unroll
    for (int bk = 0; bk < NBLK; bk++) wc[bk] = __ldg(wq + bk * (DIN * 32));
#pragma unroll 1
    for (int c = 0; c < NCH; c++) {
        if (c + 1 < NCH) {
#pragma unroll
            for (int bk = 0; bk < NBLK; bk++)
                wn[bk] = __ldg(wq + bk * (DIN * 32) + (c + 1) * 128);
        }
        unsigned long long w[NBLK][4];
#pragma unroll
        for (int bk = 0; bk < NBLK; bk++) {
            asm("mov.b64 %0,{%1,%1};" : "=l"(w[bk][0]) : "f"(wc[bk].x));
            asm("mov.b64 %0,{%1,%1};" : "=l"(w[bk][1]) : "f"(wc[bk].y));
            asm("mov.b64 %0,{%1,%1};" : "=l"(w[bk][2]) : "f"(wc[bk].z));
            asm("mov.b64 %0,{%1,%1};" : "=l"(w[bk][3]) : "f"(wc[bk].w));
        }
        const int kk = kg * NCH + c;
#pragma unroll
        for (int p = 0; p < LP; p++) {
            const ulonglong2* ip =
                reinterpret_cast<const ulonglong2*>(inb + p * 2 * DIN + 8 * kk);
            const ulonglong2 a01 = ip[0];
            const ulonglong2 a23 = ip[1];
#pragma unroll
            for (int bk = 0; bk < NBLK; bk++) {
                asm("fma.rn.f32x2 %0, %1, %2, %0;" : "+l"(acc[bk][p]) : "l"(a01.x), "l"(w[bk][0]));
                asm("fma.rn.f32x2 %0, %1, %2, %0;" : "+l"(acc[bk][p]) : "l"(a01.y), "l"(w[bk][1]));
                asm("fma.rn.f32x2 %0, %1, %2, %0;" : "+l"(acc[bk][p]) : "l"(a23.x), "l"(w[bk][2]));
                asm("fma.rn.f32x2 %0, %1, %2, %0;" : "+l"(acc[bk][p]) : "l"(a23.y), "l"(w[bk][3]));
            }
        }
#pragma unroll
        for (int bk = 0; bk < NBLK; bk++) wc[bk] = wn[bk];
    }

    if (kg > 0) {
#pragma unroll
        for (int bk = 0; bk < NBLK; bk++)
#pragma unroll
            for (int p = 0; p < LP; p++)
                *reinterpret_cast<unsigned long long*>(
                    wbuf + (((kg - 1) * NBLK + bk) * LP + p) * 256 + 2 * j) = acc[bk][p];
    }
    __syncthreads();
    if (kg == 0) {
#pragma unroll
        for (int bk = 0; bk < NBLK; bk++) {
            const float bb = __ldg(bias[bk] + j);
#pragma unroll
            for (int p = 0; p < LP; p++) {
                float lo, hi;
                asm("mov.b64 {%0,%1}, %2;" : "=f"(lo), "=f"(hi) : "l"(acc[bk][p]));
#pragma unroll
                for (int q = 0; q < 3; q++) {
                    const float2 t = *reinterpret_cast<const float2*>(
                        wbuf + ((q * NBLK + bk) * LP + p) * 256 + 2 * j);
                    lo += t.x; hi += t.y;
                }
                lo += bb; hi += bb;
                if (RELU) { lo = fmaxf(lo, 0.f); hi = fmaxf(hi, 0.f); }
                const int pr = pairBase + p;
                float* o0 = outp[bk] + (2 * pr + 0) * ocols[bk] + obase[bk] + j;
                float* o1 = outp[bk] + (2 * pr + 1) * ocols[bk] + obase[bk] + j;
                *o0 = lo; *o1 = hi;
                if (PEERMASK & (1 << bk)) { stPeer(o0, lo, prank); stPeer(o1, hi, prank); }
            }
        }
    }
    __syncthreads();
}

// ---------------- fused decoder K/V GEMM reading directly from ea/h ----------------
template<int LP>
__device__ __forceinline__ void gemmKV(const float* __restrict__ ea,
                                       const float* __restrict__ hh,
                                       const float* __restrict__ wt,
                                       const float* const* bias,
                                       float* const* outp,
                                       const int* obase,
                                       const int* ocols,
                                       float* __restrict__ wbuf,
                                       int pairBase, uint32_t prank)
{
    constexpr int DIN = 256, NBLK = 3;
    constexpr int NCH = DIN / 16;
    const int j  = threadIdx.x & 127;
    const int kg = threadIdx.x >> 7;
    const float4* wq = reinterpret_cast<const float4*>(wt) + (kg * NCH) * 128 + j;

    unsigned long long acc[NBLK][LP];
#pragma unroll
    for (int bk = 0; bk < NBLK; bk++)
#pragma unroll
        for (int p = 0; p < LP; p++) acc[bk][p] = 0ull;

    float4 wc[NBLK], wn[NBLK];
#pragma unroll
    for (int bk = 0; bk < NBLK; bk++) wc[bk] = __ldg(wq + bk * (DIN * 32));
#pragma unroll 1
    for (int c = 0; c < NCH; c++) {
        if (c + 1 < NCH) {
#pragma unroll
            for (int bk = 0; bk < NBLK; bk++)
                wn[bk] = __ldg(wq + bk * (DIN * 32) + (c + 1) * 128);
        }
        unsigned long long w[NBLK][4];
#pragma unroll
        for (int bk = 0; bk < NBLK; bk++) {
            asm("mov.b64 %0,{%1,%1};" : "=l"(w[bk][0]) : "f"(wc[bk].x));
            asm("mov.b64 %0,{%1,%1};" : "=l"(w[bk][1]) : "f"(wc[bk].y));
            asm("mov.b64 %0,{%1,%1};" : "=l"(w[bk][2]) : "f"(wc[bk].z));
            asm("mov.b64 %0,{%1,%1};" : "=l"(w[bk][3]) : "f"(wc[bk].w));
        }
        const int kk = kg * NCH + c;
        const float* src = (kk < 32) ? (ea + 8 * kk) : (hh + 8 * (kk - 32));
#pragma unroll
        for (int p = 0; p < LP; p++) {
            const ulonglong2* ip =
                reinterpret_cast<const ulonglong2*>(src + (pairBase + p) * 256);
            const ulonglong2 a01 = ip[0];
            const ulonglong2 a23 = ip[1];
#pragma unroll
            for (int bk = 0; bk < NBLK; bk++) {
                asm("fma.rn.f32x2 %0, %1, %2, %0;" : "+l"(acc[bk][p]) : "l"(a01.x), "l"(w[bk][0]));
                asm("fma.rn.f32x2 %0, %1, %2, %0;" : "+l"(acc[bk][p]) : "l"(a01.y), "l"(w[bk][1]));
                asm("fma.rn.f32x2 %0, %1, %2, %0;" : "+l"(acc[bk][p]) : "l"(a23.x), "l"(w[bk][2]));
                asm("fma.rn.f32x2 %0, %1, %2, %0;" : "+l"(acc[bk][p]) : "l"(a23.y), "l"(w[bk][3]));
            }
        }
#pragma unroll
        for (int bk = 0; bk < NBLK; bk++) wc[bk] = wn[bk];
    }

    if (kg > 0) {
#pragma unroll
        for (int bk = 0; bk < NBLK; bk++)
#pragma unroll
            for (int p = 0; p < LP; p++)
                *reinterpret_cast<unsigned long long*>(
                    wbuf + (((kg - 1) * NBLK + bk) * LP + p) * 256 + 2 * j) = acc[bk][p];
    }
    __syncthreads();
    if (kg == 0) {
#pragma unroll
        for (int bk = 0; bk < NBLK; bk++) {
            const float bb = __ldg(bias[bk] + j);
#pragma unroll
            for (int p = 0; p < LP; p++) {
                float lo, hi;
                asm("mov.b64 {%0,%1}, %2;" : "=f"(lo), "=f"(hi) : "l"(acc[bk][p]));
#pragma unroll
                for (int q = 0; q < 3; q++) {
                    const float2 t = *reinterpret_cast<const float2*>(
                        wbuf + ((q * NBLK + bk) * LP + p) * 256 + 2 * j);
                    lo += t.x; hi += t.y;
                }
                lo += bb; hi += bb;
                const int pr = pairBase + p;
                float* o0 = outp[bk] + (2 * pr + 0) * ocols[bk] + obase[bk] + j;
                float* o1 = outp[bk] + (2 * pr + 1) * ocols[bk] + obase[bk] + j;
                *o0 = lo; *o1 = hi;
                stPeer(o0, lo, prank); stPeer(o1, hi, prank);
            }
        }
    }
    __syncthreads();
}

// ---------------- K-split matvec with deep (8) weight prefetch ----------------
template<int R, bool ADD>
__device__ __forceinline__ void matvecK(const float* __restrict__ vin,
                                        const float* __restrict__ wt,
                                        const float* __restrict__ bias,
                                        float* __restrict__ out,
                                        float* __restrict__ pbuf)
{
    constexpr int NCH = R / 16;
    constexpr int DEPTH = (NCH < 8) ? NCH : 8;
    const int j  = threadIdx.x & 127;
    const int kg = threadIdx.x >> 7;
    const float4* wq = reinterpret_cast<const float4*>(wt) + (kg * NCH) * 128 + j;
    const float* vv = vin + kg * (R / 4);
    float4 wp[DEPTH];
#pragma unroll
    for (int d = 0; d < DEPTH; d++) wp[d] = __ldg(wq + d * 128);
    float a = 0.f;
#pragma unroll
    for (int c = 0; c < NCH; c++) {
        const float4 wc = wp[c % DEPTH];
        if (c + DEPTH < NCH) wp[c % DEPTH] = __ldg(wq + (c + DEPTH) * 128);
        a = fmaf(vv[4*c+0], wc.x, a);
        a = fmaf(vv[4*c+1], wc.y, a);
        a = fmaf(vv[4*c+2], wc.z, a);
        a = fmaf(vv[4*c+3], wc.w, a);
    }
    if (kg > 0) pbuf[(kg - 1) * 128 + j] = a;
    __syncthreads();
    if (kg == 0) {
        float s = a;
        s += pbuf[j];
        s += pbuf[128 + j];
        s += pbuf[256 + j];
        s += __ldg(bias + j);
        if (ADD) out[j] += s; else out[j] = s;
    }
    __syncthreads();
}

// ---------------- encoder self-attention, kt-split (2 threads per head-token) ----------------
template<int S>
__device__ __forceinline__ void attnP(const float* __restrict__ q,
                                      const float* __restrict__ k,
                                      const float* __restrict__ v,
                                      float* __restrict__ ao, int qt0, int qt1)
{
    constexpr int H0 = (S + 1) / 2;
    const int items = 16 * (qt1 - qt0);
    for (int w = threadIdx.x; w < items; w += NTH) {
        const unsigned mask = __activemask();
        const int half = w & 1;
        const int head = (w >> 1) & 7;
        const int qt   = qt0 + (w >> 4);
        const int kbeg = half ? H0 : 0;
        const int kend = half ? S : H0;
        const float* qp = q + qt * QLD + head * 16;
        unsigned long long qq[8];
#pragma unroll
        for (int u = 0; u < 4; u++) {
            const ulonglong2 t = reinterpret_cast<const ulonglong2*>(qp)[u];
            qq[2*u] = t.x; qq[2*u+1] = t.y;
        }
        float sc[H0];
        float mx = -INFINITY;
#pragma unroll
        for (int i = 0; i < H0; i++) {
            const int kt = kbeg + i;
            const ulonglong2* kp =
                reinterpret_cast<const ulonglong2*>(k + kt * QLD + head * 16);
            unsigned long long acc = 0ull;
#pragma unroll
            for (int u = 0; u < 4; u++) {
                const ulonglong2 t = kp[u];
                asm("fma.rn.f32x2 %0, %1, %2, %0;" : "+l"(acc) : "l"(qq[2*u]),   "l"(t.x));
                asm("fma.rn.f32x2 %0, %1, %2, %0;" : "+l"(acc) : "l"(qq[2*u+1]), "l"(t.y));
            }
            float lo, hi;
            asm("mov.b64 {%0,%1}, %2;" : "=f"(lo), "=f"(hi) : "l"(acc));
            float s = (lo + hi) * 0.25f;
            if (kt >= kend) s = -INFINITY;   // pad slot (odd S, second half)
            sc[i] = s;
            mx = fmaxf(mx, s);
        }
        mx = fmaxf(mx, __shfl_xor_sync(mask, mx, 1));
        float ssum = 0.f;
#pragma unroll
        for (int i = 0; i < H0; i++) {
            const float e = __expf(sc[i] - mx);
            sc[i] = e;
            ssum += e;
        }
        ssum += __shfl_xor_sync(mask, ssum, 1);
        const float inv = 1.0f / ssum;
        unsigned long long ov[8];
#pragma unroll
        for (int u = 0; u < 8; u++) ov[u] = 0ull;
#pragma unroll
        for (int i = 0; i < H0; i++) {
            const int kt = kbeg + i;
            const float pv = sc[i] * inv;
            unsigned long long pv2;
            asm("mov.b64 %0,{%1,%1};" : "=l"(pv2) : "f"(pv));
            const ulonglong2* vp =
                reinterpret_cast<const ulonglong2*>(v + ((kt < S) ? kt : 0) * QLD + head * 16);
#pragma unroll
            for (int u = 0; u < 4; u++) {
                const ulonglong2 t = vp[u];
                asm("fma.rn.f32x2 %0, %1, %2, %0;" : "+l"(ov[2*u])   : "l"(t.x), "l"(pv2));
                asm("fma.rn.f32x2 %0, %1, %2, %0;" : "+l"(ov[2*u+1]) : "l"(t.y), "l"(pv2));
            }
        }
#pragma unroll
        for (int u = 0; u < 8; u++) {
            const unsigned long long o = __shfl_xor_sync(mask, ov[u], 1);
            asm("add.rn.f32x2 %0, %0, %1;" : "+l"(ov[u]) : "l"(o));
        }
        float* aop = ao + (qt >> 1) * 256 + (qt & 1) + 2 * head * 16;
        const int u0 = half * 4;
#pragma unroll
        for (int d = 0; d < 4; d++) {
            float lo, hi;
            asm("mov.b64 {%0,%1}, %2;" : "=f"(lo), "=f"(hi) : "l"(ov[u0 + d]));
            aop[4 * (u0 + d)]     = lo;
            aop[4 * (u0 + d) + 2] = hi;
        }
    }
}

// h (interleaved) = LN(h + ob(linear)) for tokens [t0, t1)
__device__ __forceinline__ void addln(float* __restrict__ h, const float* __restrict__ ob,
                                      const float* __restrict__ g, const float* __restrict__ bt,
                                      int t0, int t1)
{
    const int warp = threadIdx.x >> 5, lane = threadIdx.x & 31;
    for (int t = t0 + warp; t < t1; t += 16) {
        float* hp = h + (t >> 1) * 256 + (t & 1);
        const float* op = ob + t * 128;
        float r[4];
        float s = 0.f;
#pragma unroll
        for (int u = 0; u < 4; u++) {
            const int j = u * 32 + lane;
            r[u] = hp[2 * j] + op[j];
            s += r[u];
        }
#pragma unroll
        for (int off = 16; off; off >>= 1) s += __shfl_xor_sync(0xffffffffu, s, off);
        const float mu = s * (1.0f / 128.0f);
        float vs = 0.f;
#pragma unroll
        for (int u = 0; u < 4; u++) { const float d = r[u] - mu; vs = fmaf(d, d, vs); }
#pragma unroll
        for (int off = 16; off; off >>= 1) vs += __shfl_xor_sync(0xffffffffu, vs, off);
        const float rs = rsqrtf(vs * (1.0f / 128.0f) + 1e-5f);
#pragma unroll
        for (int u = 0; u < 4; u++) {
            const int j = u * 32 + lane;
            hp[2 * j] = fmaf(g[j] * (r[u] - mu), rs, bt[j]);
        }
    }
}

// token embedding for tokens [t0, t1); pads (state t>=37) zeroed
template<bool ACTION>
__device__ __forceinline__ void embed(float* __restrict__ h,
                                      const float* __restrict__ tcx,
                                      const float* __restrict__ tcy,
                                      const float* __restrict__ W,
                                      const float* __restrict__ b,
                                      int t0, int t1)
{
    const int total = (t1 - t0) * 128;
    for (int idx = threadIdx.x; idx < total; idx += NTH) {
        const int t = t0 + (idx >> 7), j = idx & 127;
        float val = 0.f;
        if (ACTION || t < SSQ) {
            const int c = ACTION ? (t < KA ? t : KS) : t;
            val = fmaf(tcx[c], __ldg(W + j), fmaf(tcy[c], __ldg(W + 128 + j), __ldg(b + j)));
        }
        h[(t >> 1) * 256 + 2 * j + (t & 1)] = val;
    }
}

// 2-layer encoder on own token rows; k,v peer-replicated for attention
template<int S, int PTOT, int PAIRB, int T0, int T1>
__device__ __forceinline__ void encode(float* __restrict__ h, float* __restrict__ scr,
                                       float* __restrict__ ob, float* __restrict__ wbuf,
                                       int attnOff, const float* attnB,
                                       int w1Off, const float* b1,
                                       int w2Off, const float* b2,
                                       const float* ln, uint32_t prank)
{
    float* q  = scr;
    float* k  = scr + 5280;    // 40 * QLD
    float* v  = scr + 10560;
    float* ao = ob;            // attention output shares ob buffer (gemmK in-place safe)
    const int oc128[4] = {128, 128, 128, 128};
    const int ocQKV[3] = {QLD, QLD, QLD};
    const int oc512[4] = {512, 512, 512, 512};
    const int ob0[4]   = {0, 0, 0, 0};
    const int obF[4]   = {0, 128, 256, 384};
#pragma unroll 1
    for (int l = 0; l < 2; l++) {
        const float* Wqkv = g_wt + attnOff + (l * 4 + 0) * 16384;
        const float* Wo   = g_wt + attnOff + (l * 4 + 3) * 16384;
        const float* biasQKV[3] = { attnB + (l * 4 + 0) * 128,
                                    attnB + (l * 4 + 1) * 128,
                                    attnB + (l * 4 + 2) * 128 };
        const float* biasO[1] = { attnB + (l * 4 + 3) * 128 };
        float* outQKV[3] = { q, k, v };
        float* outO[1]   = { ob };

        CLUSTER_SYNC();   // peer done reading its k,v copy; safe to overwrite via stPeer
        gemmF<PTOT, 128, 3, 4, false, true, 6>(h, Wqkv, biasQKV, outQKV, ob0, ocQKV,
                                               wbuf, PAIRB, prank);
        CLUSTER_SYNC();   // full k,v present in both CTAs
        attnP<S>(q, k, v, ao, T0, T1);
        __syncthreads();
        gemmK<PTOT, 128, 1, false, 0>(ao, Wo, biasO, outO, ob0, oc128,
                                      wbuf, PAIRB, prank);
        addln(h, ob, ln + (l * 2 + 0) * 256, ln + (l * 2 + 0) * 256 + 128, T0, T1);
        __syncthreads();

        const float* W1b = g_wt + w1Off + l * 65536;
        const float* b1b = b1 + l * 512;
        const float* biasF1[4] = { b1b, b1b + 128, b1b + 256, b1b + 384 };
        float* outF1[4] = { scr, scr, scr, scr };
        gemmF<PTOT, 128, 4, 4, true, false, 0>(h, W1b, biasF1, outF1, obF, oc512,
                                               wbuf, PAIRB, prank);
        const float* biasF2[1] = { b2 + l * 128 };
        float* outF2[1] = { ob };
        gemmK<PTOT, 512, 1, false, 0>(scr, g_wt + w2Off + l * 65536, biasF2,
                                      outF2, ob0, oc128, wbuf, PAIRB, prank);
        addln(h, ob, ln + (l * 2 + 1) * 256, ln + (l * 2 + 1) * 256 + 128, T0, T1);
        __syncthreads();
    }
}

extern __shared__ float sm[];

__global__ void __launch_bounds__(NTH, 1) __cluster_dims__(2, 1, 1) tsp_kernel(Params p)
{
    const int b = blockIdx.x >> 1, tid = threadIdx.x;
    const uint32_t rank = blockIdx.x & 1, prank = rank ^ 1;
    const int B = gridDim.x >> 1;

    float* xsx  = sm + O_XSX;
    float* xsy  = sm + O_XSY;
    float* h    = sm + O_H;
    float* scr  = sm + O_SCR;
    float* ob   = sm + O_OB;
    float* ea   = sm + O_EA;
    float* Kb   = sm + O_KB;
    float* Vb   = sm + O_VB;
    float* eq   = sm + O_EQ;
    float* hdec = sm + O_HDEC;
    float* q2   = sm + O_Q2;
    float* odec = sm + O_ODEC;
    float* sc   = sm + O_SCT;
    float* lg   = sm + O_LG;
    float* tcx  = sm + O_TCX;
    float* tcy  = sm + O_TCY;
    float* misc = sm + O_MISC;
    float* wbuf = sm + O_WBUF;
    int* knn   = (int*)(sm + O_INT);
    int* valid = knn + 35;
    int* mask  = knn + 50;

    for (int n = tid; n < NN; n += NTH) {
        xsx[n] = p.x[(b * NN + n) * 2 + 0];
        xsy[n] = p.x[(b * NN + n) * 2 + 1];
        mask[n] = 1;
    }
    __syncthreads();
    if (tid == 0) {
        const int st = p.start[b];
        mask[st] = 0;
        misc[0] = xsx[st]; misc[1] = xsy[st];
        misc[2] = xsx[st]; misc[3] = xsy[st];
        misc[4] = 0.f;
        if (rank == 0) p.out[b * NN] = (float)st;
    }
    __syncthreads();

    for (int step = 0; step < NN - 1; step++) {
        const float lastx = misc[0], lasty = misc[1];

        float* d2 = scr;
        if (tid < NN) {
            const float dx = xsx[tid] - lastx, dy = xsy[tid] - lasty;
            d2[tid] = mask[tid] ? (dx * dx + dy * dy) : 1e9f;
        }
        __syncthreads();

        // top-35 smallest (d2, idx), jax tie order — replicated in both CTAs
        if (tid < 32) {
            unsigned long long k0 = ~0ull, k1 = ~0ull;
            if (tid < NN)      k0 = (((unsigned long long)__float_as_uint(d2[tid]))      << 32) | (unsigned)tid;
            if (tid + 32 < NN) k1 = (((unsigned long long)__float_as_uint(d2[tid + 32])) << 32) | (unsigned)(tid + 32);
            for (int r = 0; r < KS; r++) {
                unsigned long long m = k0 < k1 ? k0 : k1;
#pragma unroll
                for (int off = 16; off; off >>= 1) {
                    unsigned long long o = __shfl_xor_sync(0xffffffffu, m, off);
                    if (o < m) m = o;
                }
                if (k0 == m) k0 = ~0ull;
                if (k1 == m) k1 = ~0ull;
                if (tid == 0) knn[r] = (int)(m & 0xffffffffull);
            }
        }
        __syncthreads();

        if (tid < KS) { const int n = knn[tid]; tcx[tid] = xsx[n]; tcy[tid] = xsy[n]; }
        if (tid < KA) valid[tid] = mask[knn[tid]];
        if (tid == 0) { tcx[35] = lastx; tcy[35] = lasty; tcx[36] = misc[2]; tcy[36] = misc[3]; }
        __syncthreads();

        // ---- ACTION encoder (16 tokens, 8/8 split) ----
        embed<true>(h, tcx, tcy, p.aEmbW, p.aEmbB, (int)rank * 8, (int)rank * 8 + 8);
        __syncthreads();
        if (rank == 0)
            encode<SAQ, 4, 0, 0, 8>(h, scr, ob, wbuf, OFF_AATTN, p.aAttnB,
                                    OFF_AW1, p.aB1, OFF_AW2, p.aB2, p.aLn, prank);
        else
            encode<SAQ, 4, 4, 8, 16>(h, scr, ob, wbuf, OFF_AATTN, p.aAttnB,
                                     OFF_AW1, p.aB1, OFF_AW2, p.aB2, p.aLn, prank);
        // copy own SA rows to ea
        for (int i = tid + (int)rank * 1024; i < 1024 + (int)rank * 1024; i += NTH) ea[i] = h[i];
        __syncthreads();

        // ---- STATE encoder (37 tokens: balanced 20/17 split, pairs 10/10) ----
        embed<false>(h, tcx, tcy, p.sEmbW, p.sEmbB, rank ? 20 : 0, rank ? 40 : 20);
        __syncthreads();
        if (rank == 0)
            encode<SSQ, 10, 0, 0, 20>(h, scr, ob, wbuf, OFF_SATTN, p.sAttnB,
                                      OFF_SW1, p.sB1, OFF_SW2, p.sB2, p.sLn, prank);
        else
            encode<SSQ, 10, 10, 20, 37>(h, scr, ob, wbuf, OFF_SATTN, p.sAttnB,
                                        OFF_SW1, p.sB1, OFF_SW2, p.sB2, p.sLn, prank);

        // ---- exchange encoder outputs (64-bit packed DSMEM stores) ----
        // rank0 owns h rows 0..19 -> sends rows 0..15 (pairs 0..7)
        // rank1 owns h rows 20..39 -> sends pairs 17,18 (rows 34..37)
        {
            const unsigned long long* eaU = reinterpret_cast<const unsigned long long*>(ea);
            const unsigned long long* hU  = reinterpret_cast<const unsigned long long*>(h);
            if (rank == 0) {
                for (int i = tid; i < 512;  i += NTH) stPeer2(eaU + i, eaU[i], prank);
                for (int i = tid; i < 1024; i += NTH) stPeer2(hU + i, hU[i], prank);
            } else {
                for (int i = tid; i < 512; i += NTH) stPeer2(eaU + 512 + i, eaU[512 + i], prank);
                for (int i = tid; i < 256; i += NTH) stPeer2(hU + 2176 + i, hU[2176 + i], prank);
            }
        }
        CLUSTER_SYNC();

        // ---- eq = [ea row15 | h row35 | h row36] — replicated ----
        if (tid < 128) {
            eq[tid]       = ea[7 * 256 + 2 * tid + 1];
            eq[128 + tid] = h[17 * 256 + 2 * tid + 1];
            eq[256 + tid] = h[18 * 256 + 2 * tid + 0];
        }
        __syncthreads();

        // ---- h_dec = emb_q @ Wq_mlp + bq_mlp (K-split) ----
        matvecK<384, false>(eq, g_wt + OFF_WQM, p.bqm, hdec, wbuf);

        // ---- K (256 cols) & V (128 cols), fused K-split directly from ea/h ----
        {
            const float* biasKV[3] = { p.bK, p.bK + 128, p.bV };
            float* outKV[3] = { Kb, Kb, Vb };
            const int obKV[3] = { 0, 128, 0 };
            const int ocKV[3] = { 256, 256, 128 };
            gemmKV<4>(ea, h, g_wt + OFF_WK, biasKV, outKV, obKV, ocKV, wbuf,
                      (int)rank * 4, prank);
        }
        CLUSTER_SYNC();   // full Kb, Vb in both CTAs

        // ---- decoder layer 0 (replicated) ----
        matvecK<128, false>(hdec, g_wt + OFF_DWQ, p.dbq, q2, wbuf);
        if (tid < 120) {
            const int head = tid & 7, kk = tid >> 3;
            float s = 0.f;
            const float* kp = Kb + kk * 256 + head * 16;
#pragma unroll
            for (int d = 0; d < 16; d++) s = fmaf(q2[head * 16 + d], kp[d], s);
            s *= 0.25f;
            sc[head * 15 + kk] = valid[kk] ? s : -1e9f;
        }
        __syncthreads();
        if (tid < 8) {
            float mx = -INFINITY;
            for (int kk = 0; kk < KA; kk++) mx = fmaxf(mx, sc[tid * 15 + kk]);
            float ssum = 0.f;
            for (int kk = 0; kk < KA; kk++) {
                const float e = __expf(sc[tid * 15 + kk] - mx);
                sc[tid * 15 + kk] = e;
                ssum += e;
            }
            const float inv = 1.0f / ssum;
            for (int kk = 0; kk < KA; kk++) sc[tid * 15 + kk] *= inv;
        }
        __syncthreads();
        if (tid < 128) {
            const int head = tid >> 4, d = tid & 15;
            float o = 0.f;
            for (int kk = 0; kk < KA; kk++)
                o = fmaf(sc[head * 15 + kk], Vb[kk * 128 + head * 16 + d], o);
            odec[tid] = o;
        }
        __syncthreads();
        matvecK<128, true>(odec, g_wt + OFF_DWO, p.dbo, hdec, wbuf);

        // ---- final pointer layer ----
        matvecK<128, false>(hdec, g_wt + OFF_DWQ + 16384, p.dbq + 128, q2, wbuf);
        if (tid < 480) {
            const int w = tid >> 5, l = tid & 31;
            const float4 qv = *reinterpret_cast<const float4*>(q2 + 4 * l);
            const float4 kv = *reinterpret_cast<const float4*>(Kb + w * 256 + 128 + 4 * l);
            float s = 0.f;
            s = fmaf(qv.x, kv.x, s);
            s = fmaf(qv.y, kv.y, s);
            s = fmaf(qv.z, kv.z, s);
            s = fmaf(qv.w, kv.w, s);
#pragma unroll
            for (int off = 16; off; off >>= 1) s += __shfl_xor_sync(0xffffffffu, s, off);
            if (l == 0) {
                s *= 0.08838834764831845f;
                s = 10.0f * tanhf(s);
                lg[w] = valid[w] ? s : -1e9f;
            }
        }
        __syncthreads();
        if (tid == 0) {
            float mx = -INFINITY; int best = 0;
            for (int kk = 0; kk < KA; kk++)
                if (lg[kk] > mx) { mx = lg[kk]; best = kk; }
            float ssum = 0.f, eb = 0.f;
            for (int kk = 0; kk < KA; kk++) {
                const float e = __expf(lg[kk] - mx);
                ssum += e;
                if (kk == best) eb = e;
            }
            misc[4] += __logf(eb / ssum);
            const int nxt = knn[best];
            mask[nxt] = 0;
            misc[0] = xsx[nxt]; misc[1] = xsy[nxt];
            if (rank == 0) p.out[b * NN + step + 1] = (float)nxt;
        }
        __syncthreads();
    }

    if (rank == 0 && tid == 0) p.out[B * NN + b] = misc[4];
    CLUSTER_SYNC();
}

extern "C" void kernel_launch(void* const* d_in, const int* in_sizes, int n_in,
                              void* d_out, int out_size)
{
    int i = 2;
    if (n_in > 2 && in_sizes[2] == 1) i = 4;

    TQJobs jb;
    const float* srcs[11] = {
        (const float*)d_in[i+2],   // aAttnW
        (const float*)d_in[i+11],  // sAttnW
        (const float*)d_in[i+4],   // aW1
        (const float*)d_in[i+13],  // sW1
        (const float*)d_in[i+6],   // aW2
        (const float*)d_in[i+15],  // sW2
        (const float*)d_in[i+18],  // WK
        (const float*)d_in[i+20],  // WV
        (const float*)d_in[i+22],  // Wqm
        (const float*)d_in[i+24],  // dWq
        (const float*)d_in[i+26],  // dWo
    };
    const int offs[11]  = {OFF_AATTN, OFF_SATTN, OFF_AW1, OFF_SW1, OFF_AW2, OFF_SW2,
                           OFF_WK, OFF_WV, OFF_WQM, OFF_DWQ, OFF_DWO};
    const int Rs[11]    = {128, 128, 128, 128, 512, 512, 256, 256, 384, 128, 128};
    const int Cs[11]    = {128, 128, 512, 512, 128, 128, 256, 256, 128, 128, 128};
    const int nms[11]   = {8, 8, 2, 2, 2, 2, 1, 1, 1, 2, 2};
    for (int s = 0; s < 11; s++) {
        jb.src[s] = srcs[s]; jb.dstOff[s] = offs[s];
        jb.R[s] = Rs[s]; jb.C[s] = Cs[s]; jb.nmat[s] = nms[s];
    }
    tq_all<<<128, 256>>>(jb);

    Params p;
    p.x = (const float*)d_in[0];
    p.start = (const int*)d_in[1];
    p.aEmbW = (const float*)d_in[i+0];  p.aEmbB = (const float*)d_in[i+1];
    p.aAttnB = (const float*)d_in[i+3];
    p.aB1 = (const float*)d_in[i+5];    p.aB2 = (const float*)d_in[i+7];
    p.aLn = (const float*)d_in[i+8];
    p.sEmbW = (const float*)d_in[i+9];  p.sEmbB = (const float*)d_in[i+10];
    p.sAttnB = (const float*)d_in[i+12];
    p.sB1 = (const float*)d_in[i+14];   p.sB2 = (const float*)d_in[i+16];
    p.sLn = (const float*)d_in[i+17];
    p.bK  = (const float*)d_in[i+19];
    p.bV  = (const float*)d_in[i+21];
    p.bqm = (const float*)d_in[i+23];
    p.dbq = (const float*)d_in[i+25];
    p.dbo = (const float*)d_in[i+27];
    p.out = (float*)d_out;

    cudaFuncSetAttribute(tsp_kernel, cudaFuncAttributeMaxDynamicSharedMemorySize, SMEM_BYTES);

    const int B = in_sizes[1];
    tsp_kernel<<<2 * B, NTH, SMEM_BYTES>>>(p);
}

// round 16
// speedup vs baseline: 1.0821x; 1.0821x over previous
#include <cuda_runtime.h>
#include <math.h>
#include <stdint.h>

#define NTH 512
#define NN  50
#define KA  15
#define KS  35
#define SAQ 16
#define SSQ 37
#define QLD 132   // q/k/v row stride (floats): bank-conflict-free attention

// ------------- transposed weight scratch (block-contiguous quad layout) -------------
#define OFF_AATTN 0
#define OFF_SATTN 131072
#define OFF_AW1   262144
#define OFF_SW1   393216
#define OFF_AW2   524288
#define OFF_SW2   655360
#define OFF_WK    786432
#define OFF_WV    851968
#define OFF_WQM   917504
#define OFF_DWQ   966656
#define OFF_DWO   999424
#define WT_TOTAL  1032192

__device__ float g_wt[WT_TOTAL];

// ---------------- shared memory layout (float offsets) ----------------
#define O_XSX  0
#define O_XSY  64
#define O_H    128        // 40x128 interleaved = 5120
#define O_SCR  5248       // 20480: q@0,k@5280,v@10560 (stride 132); FF1; d2
#define O_OB   25728      // 5120 (also holds attention output ao, interleaved)
#define O_EA   30848      // 2048
#define O_KB   32896      // 4096
#define O_VB   36992      // 2048
#define O_EQ   39040      // 384
#define O_HDEC 39424
#define O_Q2   39552
#define O_ODEC 39680
#define O_SCT  39808
#define O_LG   39936
#define O_TCX  39952
#define O_TCY  39992
#define O_MISC 40032
#define O_INT  40040      // ints
#define O_WBUF 40144      // 16384 floats (64KB): gemmF staging / gemmK & matvecK partials
#define SMEM_FLOATS 56528
#define SMEM_BYTES (SMEM_FLOATS * 4)

struct Params {
    const float* x; const int* start;
    const float *aEmbW, *aEmbB, *aAttnB, *aB1, *aB2, *aLn;
    const float *sEmbW, *sEmbB, *sAttnB, *sB1, *sB2, *sLn;
    const float *bK, *bV, *bqm, *dbq, *dbo;
    float* out;
};

// ---------------- cluster helpers ----------------
__device__ __forceinline__ uint32_t smaddr(const void* p){
    uint32_t a;
    asm("{ .reg .u64 t; cvta.to.shared.u64 t, %1; cvt.u32.u64 %0, t; }" : "=r"(a) : "l"(p));
    return a;
}
__device__ __forceinline__ void stPeer(const void* lp, float v, uint32_t prank){
    uint32_t l = smaddr(lp), r;
    asm("mapa.shared::cluster.u32 %0, %1, %2;" : "=r"(r) : "r"(l), "r"(prank));
    asm volatile("st.shared::cluster.f32 [%0], %1;" :: "r"(r), "f"(v) : "memory");
}
__device__ __forceinline__ void stPeer2(const void* lp, unsigned long long v, uint32_t prank){
    uint32_t l = smaddr(lp), r;
    asm("mapa.shared::cluster.u32 %0, %1, %2;" : "=r"(r) : "r"(l), "r"(prank));
    asm volatile("st.shared::cluster.b64 [%0], %1;" :: "r"(r), "l"(v) : "memory");
}
#define CLUSTER_SYNC() do { \
    asm volatile("barrier.cluster.arrive.aligned;" ::: "memory"); \
    asm volatile("barrier.cluster.wait.aligned;" ::: "memory"); } while(0)

// ---------------- merged weight-transpose prologue ----------------
struct TQJobs {
    const float* src[11];
    int dstOff[11], R[11], C[11], nmat[11];
};

__global__ void tq_all(TQJobs jb)
{
#pragma unroll 1
    for (int s = 0; s < 11; s++) {
        const int R = jb.R[s], C = jb.C[s];
        const int total = jb.nmat[s] * R * C;
        const float* __restrict__ src = jb.src[s];
        const int dstOff = jb.dstOff[s];
        for (int idx = blockIdx.x * blockDim.x + threadIdx.x; idx < total;
             idx += gridDim.x * blockDim.x) {
            const int m = idx / (R * C);
            const int rem = idx - m * R * C;
            const int r = rem / C;
            const int c = rem - r * C;
            g_wt[dstOff + m * R * C + (c >> 7) * (R * 128)
                 + ((r >> 2) << 9) + ((c & 127) << 2) + (r & 3)] = src[idx];
        }
    }
}

// ---------------- fused multi-block smem-staged packed-f32x2 GEMM ----------------
template<int PPG, int DIN, int NBLK, int TC, bool RELU, bool LINOUT, int PEERMASK>
__device__ __forceinline__ void gemmF(const float* __restrict__ in,
                                      const float* __restrict__ wt,
                                      const float* const* bias,
                                      float* const* outp,
                                      const int* obase,
                                      const int* ocols,
                                      float* __restrict__ wbuf,
                                      int pairBase, uint32_t prank)
{
    constexpr int T    = DIN / (4 * TC);
    constexpr int BUF4 = NBLK * TC * 128;
    constexpr int F4PT = BUF4 / NTH;
    const int j = threadIdx.x & 127;
    const int g = threadIdx.x >> 7;
    const float* inb = in + (pairBase + g * PPG) * 2 * DIN;
    const float4* wg4 = reinterpret_cast<const float4*>(wt);
    float4* wb4 = reinterpret_cast<float4*>(wbuf);

    float4 pre[F4PT];
#pragma unroll
    for (int s = 0; s < F4PT; s++) {
        const int idx = threadIdx.x + s * NTH;
        const int bk = idx / (TC * 128);
        const int rem = idx - bk * (TC * 128);
        pre[s] = __ldg(wg4 + bk * (DIN * 32) + rem);
    }
    unsigned long long acc[NBLK][PPG];
#pragma unroll
    for (int bk = 0; bk < NBLK; bk++)
#pragma unroll
        for (int p = 0; p < PPG; p++) acc[bk][p] = 0ull;

#pragma unroll 1
    for (int t = 0; t < T; t++) {
        float4* wb = wb4 + (t & 1) * BUF4;
#pragma unroll
        for (int s = 0; s < F4PT; s++) wb[threadIdx.x + s * NTH] = pre[s];
        __syncthreads();
        if (t + 1 < T) {
#pragma unroll
            for (int s = 0; s < F4PT; s++) {
                const int idx = threadIdx.x + s * NTH;
                const int bk = idx / (TC * 128);
                const int rem = idx - bk * (TC * 128);
                pre[s] = __ldg(wg4 + bk * (DIN * 32) + (t + 1) * (TC * 128) + rem);
            }
        }
#pragma unroll
        for (int ci = 0; ci < TC; ci++) {
            const int kk = t * TC + ci;
            ulonglong2 a01[PPG], a23[PPG];
#pragma unroll
            for (int p = 0; p < PPG; p++) {
                const ulonglong2* ip =
                    reinterpret_cast<const ulonglong2*>(inb + p * 2 * DIN + 8 * kk);
                a01[p] = ip[0];
                a23[p] = ip[1];
            }
#pragma unroll
            for (int bk = 0; bk < NBLK; bk++) {
                const float4 w = wb[bk * (TC * 128) + ci * 128 + j];
                unsigned long long w0, w1, w2, w3;
                asm("mov.b64 %0,{%1,%1};" : "=l"(w0) : "f"(w.x));
                asm("mov.b64 %0,{%1,%1};" : "=l"(w1) : "f"(w.y));
                asm("mov.b64 %0,{%1,%1};" : "=l"(w2) : "f"(w.z));
                asm("mov.b64 %0,{%1,%1};" : "=l"(w3) : "f"(w.w));
#pragma unroll
                for (int p = 0; p < PPG; p++) {
                    asm("fma.rn.f32x2 %0, %1, %2, %0;" : "+l"(acc[bk][p]) : "l"(a01[p].x), "l"(w0));
                    asm("fma.rn.f32x2 %0, %1, %2, %0;" : "+l"(acc[bk][p]) : "l"(a01[p].y), "l"(w1));
                    asm("fma.rn.f32x2 %0, %1, %2, %0;" : "+l"(acc[bk][p]) : "l"(a23[p].x), "l"(w2));
                    asm("fma.rn.f32x2 %0, %1, %2, %0;" : "+l"(acc[bk][p]) : "l"(a23[p].y), "l"(w3));
                }
            }
        }
    }
#pragma unroll
    for (int bk = 0; bk < NBLK; bk++) {
        const float bb = __ldg(bias[bk] + j);
#pragma unroll
        for (int p = 0; p < PPG; p++) {
            float lo, hi;
            asm("mov.b64 {%0,%1}, %2;" : "=f"(lo), "=f"(hi) : "l"(acc[bk][p]));
            lo += bb; hi += bb;
            if (RELU) { lo = fmaxf(lo, 0.f); hi = fmaxf(hi, 0.f); }
            const int pr = pairBase + g * PPG + p;
            if (LINOUT) {
                float* o0 = outp[bk] + (2 * pr + 0) * ocols[bk] + obase[bk] + j;
                float* o1 = outp[bk] + (2 * pr + 1) * ocols[bk] + obase[bk] + j;
                *o0 = lo; *o1 = hi;
                if (PEERMASK & (1 << bk)) { stPeer(o0, lo, prank); stPeer(o1, hi, prank); }
            } else {
                *reinterpret_cast<float2*>(outp[bk] + pr * 2 * ocols[bk]
                                           + 2 * (obase[bk] + j)) = make_float2(lo, hi);
            }
        }
    }
    __syncthreads();
}

// ---------------- K-split packed-f32x2 GEMM (direct-LDG weights, depth-4 prefetch) ----------------
template<int LP, int DIN, int NBLK, bool RELU, int PEERMASK>
__device__ __forceinline__ void gemmK(const float* __restrict__ in,
                                      const float* __restrict__ wt,
                                      const float* const* bias,
                                      float* const* outp,
                                      const int* obase,
                                      const int* ocols,
                                      float* __restrict__ wbuf,
                                      int pairBase, uint32_t prank)
{
    constexpr int NCH = DIN / 16;
    constexpr int DEPTH = (NCH < 4) ? NCH : 4;
    const int j  = threadIdx.x & 127;
    const int kg = threadIdx.x >> 7;
    const float* inb = in + pairBase * 2 * DIN;
    const float4* wq = reinterpret_cast<const float4*>(wt) + (kg * NCH) * 128 + j;

    unsigned long long acc[NBLK][LP];
#pragma unroll
    for (int bk = 0; bk < NBLK; bk++)
#pragma unroll
        for (int p = 0; p < LP; p++) acc[bk][p] = 0ull;

    float4 wp[NBLK][DEPTH];
#pragma unroll
    for (int bk = 0; bk < NBLK; bk++)
#pragma unroll
        for (int d = 0; d < DEPTH; d++)
            wp[bk][d] = __ldg(wq + bk * (DIN * 32) + d * 128);
#pragma unroll 4
    for (int c = 0; c < NCH; c++) {
        unsigned long long w[NBLK][4];
#pragma unroll
        for (int bk = 0; bk < NBLK; bk++) {
            const float4 wc = wp[bk][c % DEPTH];
            if (c + DEPTH < NCH)
                wp[bk][c % DEPTH] = __ldg(wq + bk * (DIN * 32) + (c + DEPTH) * 128);
            asm("mov.b64 %0,{%1,%1};" : "=l"(w[bk][0]) : "f"(wc.x));
            asm("mov.b64 %0,{%1,%1};" : "=l"(w[bk][1]) : "f"(wc.y));
            asm("mov.b64 %0,{%1,%1};" : "=l"(w[bk][2]) : "f"(wc.z));
            asm("mov.b64 %0,{%1,%1};" : "=l"(w[bk][3]) : "f"(wc.w));
        }
        const int kk = kg * NCH + c;
#pragma unroll
        for (int p = 0; p < LP; p++) {
            const ulonglong2* ip =
                reinterpret_cast<const ulonglong2*>(inb + p * 2 * DIN + 8 * kk);
            const ulonglong2 a01 = ip[0];
            const ulonglong2 a23 = ip[1];
#pragma unroll
            for (int bk = 0; bk < NBLK; bk++) {
                asm("fma.rn.f32x2 %0, %1, %2, %0;" : "+l"(acc[bk][p]) : "l"(a01.x), "l"(w[bk][0]));
                asm("fma.rn.f32x2 %0, %1, %2, %0;" : "+l"(acc[bk][p]) : "l"(a01.y), "l"(w[bk][1]));
                asm("fma.rn.f32x2 %0, %1, %2, %0;" : "+l"(acc[bk][p]) : "l"(a23.x), "l"(w[bk][2]));
                asm("fma.rn.f32x2 %0, %1, %2, %0;" : "+l"(acc[bk][p]) : "l"(a23.y), "l"(w[bk][3]));
            }
        }
    }

    if (kg > 0) {
#pragma unroll
        for (int bk = 0; bk < NBLK; bk++)
#pragma unroll
            for (int p = 0; p < LP; p++)
                *reinterpret_cast<unsigned long long*>(
                    wbuf + (((kg - 1) * NBLK + bk) * LP + p) * 256 + 2 * j) = acc[bk][p];
    }
    __syncthreads();
    if (kg == 0) {
#pragma unroll
        for (int bk = 0; bk < NBLK; bk++) {
            const float bb = __ldg(bias[bk] + j);
#pragma unroll
            for (int p = 0; p < LP; p++) {
                float lo, hi;
                asm("mov.b64 {%0,%1}, %2;" : "=f"(lo), "=f"(hi) : "l"(acc[bk][p]));
#pragma unroll
                for (int q = 0; q < 3; q++) {
                    const float2 t = *reinterpret_cast<const float2*>(
                        wbuf + ((q * NBLK + bk) * LP + p) * 256 + 2 * j);
                    lo += t.x; hi += t.y;
                }
                lo += bb; hi += bb;
                if (RELU) { lo = fmaxf(lo, 0.f); hi = fmaxf(hi, 0.f); }
                const int pr = pairBase + p;
                float* o0 = outp[bk] + (2 * pr + 0) * ocols[bk] + obase[bk] + j;
                float* o1 = outp[bk] + (2 * pr + 1) * ocols[bk] + obase[bk] + j;
                *o0 = lo; *o1 = hi;
                if (PEERMASK & (1 << bk)) { stPeer(o0, lo, prank); stPeer(o1, hi, prank); }
            }
        }
    }
    __syncthreads();
}

// ---------------- fused decoder K/V GEMM reading directly from ea/h ----------------
template<int LP>
__device__ __forceinline__ void gemmKV(const float* __restrict__ ea,
                                       const float* __restrict__ hh,
                                       const float* __restrict__ wt,
                                       const float* const* bias,
                                       float* const* outp,
                                       const int* obase,
                                       const int* ocols,
                                       float* __restrict__ wbuf,
                                       int pairBase, uint32_t prank)
{
    constexpr int DIN = 256, NBLK = 3;
    constexpr int NCH = DIN / 16;
    const int j  = threadIdx.x & 127;
    const int kg = threadIdx.x >> 7;
    const float4* wq = reinterpret_cast<const float4*>(wt) + (kg * NCH) * 128 + j;

    unsigned long long acc[NBLK][LP];
#pragma unroll
    for (int bk = 0; bk < NBLK; bk++)
#pragma unroll
        for (int p = 0; p < LP; p++) acc[bk][p] = 0ull;

    float4 wc[NBLK], wn[NBLK];
#pragma unroll
    for (int bk = 0; bk < NBLK; bk++) wc[bk] = __ldg(wq + bk * (DIN * 32));
#pragma unroll 1
    for (int c = 0; c < NCH; c++) {
        if (c + 1 < NCH) {
#pragma unroll
            for (int bk = 0; bk < NBLK; bk++)
                wn[bk] = __ldg(wq + bk * (DIN * 32) + (c + 1) * 128);
        }
        unsigned long long w[NBLK][4];
#pragma unroll
        for (int bk = 0; bk < NBLK; bk++) {
            asm("mov.b64 %0,{%1,%1};" : "=l"(w[bk][0]) : "f"(wc[bk].x));
            asm("mov.b64 %0,{%1,%1};" : "=l"(w[bk][1]) : "f"(wc[bk].y));
            asm("mov.b64 %0,{%1,%1};" : "=l"(w[bk][2]) : "f"(wc[bk].z));
            asm("mov.b64 %0,{%1,%1};" : "=l"(w[bk][3]) : "f"(wc[bk].w));
        }
        const int kk = kg * NCH + c;
        const float* src = (kk < 32) ? (ea + 8 * kk) : (hh + 8 * (kk - 32));
#pragma unroll
        for (int p = 0; p < LP; p++) {
            const ulonglong2* ip =
                reinterpret_cast<const ulonglong2*>(src + (pairBase + p) * 256);
            const ulonglong2 a01 = ip[0];
            const ulonglong2 a23 = ip[1];
#pragma unroll
            for (int bk = 0; bk < NBLK; bk++) {
                asm("fma.rn.f32x2 %0, %1, %2, %0;" : "+l"(acc[bk][p]) : "l"(a01.x), "l"(w[bk][0]));
                asm("fma.rn.f32x2 %0, %1, %2, %0;" : "+l"(acc[bk][p]) : "l"(a01.y), "l"(w[bk][1]));
                asm("fma.rn.f32x2 %0, %1, %2, %0;" : "+l"(acc[bk][p]) : "l"(a23.x), "l"(w[bk][2]));
                asm("fma.rn.f32x2 %0, %1, %2, %0;" : "+l"(acc[bk][p]) : "l"(a23.y), "l"(w[bk][3]));
            }
        }
#pragma unroll
        for (int bk = 0; bk < NBLK; bk++) wc[bk] = wn[bk];
    }

    if (kg > 0) {
#pragma unroll
        for (int bk = 0; bk < NBLK; bk++)
#pragma unroll
            for (int p = 0; p < LP; p++)
                *reinterpret_cast<unsigned long long*>(
                    wbuf + (((kg - 1) * NBLK + bk) * LP + p) * 256 + 2 * j) = acc[bk][p];
    }
    __syncthreads();
    if (kg == 0) {
#pragma unroll
        for (int bk = 0; bk < NBLK; bk++) {
            const float bb = __ldg(bias[bk] + j);
#pragma unroll
            for (int p = 0; p < LP; p++) {
                float lo, hi;
                asm("mov.b64 {%0,%1}, %2;" : "=f"(lo), "=f"(hi) : "l"(acc[bk][p]));
#pragma unroll
                for (int q = 0; q < 3; q++) {
                    const float2 t = *reinterpret_cast<const float2*>(
                        wbuf + ((q * NBLK + bk) * LP + p) * 256 + 2 * j);
                    lo += t.x; hi += t.y;
                }
                lo += bb; hi += bb;
                const int pr = pairBase + p;
                float* o0 = outp[bk] + (2 * pr + 0) * ocols[bk] + obase[bk] + j;
                float* o1 = outp[bk] + (2 * pr + 1) * ocols[bk] + obase[bk] + j;
                *o0 = lo; *o1 = hi;
                stPeer(o0, lo, prank); stPeer(o1, hi, prank);
            }
        }
    }
    __syncthreads();
}

// ---------------- K-split matvec with deep (8) weight prefetch ----------------
template<int R, bool ADD>
__device__ __forceinline__ void matvecK(const float* __restrict__ vin,
                                        const float* __restrict__ wt,
                                        const float* __restrict__ bias,
                                        float* __restrict__ out,
                                        float* __restrict__ pbuf)
{
    constexpr int NCH = R / 16;
    constexpr int DEPTH = (NCH < 8) ? NCH : 8;
    const int j  = threadIdx.x & 127;
    const int kg = threadIdx.x >> 7;
    const float4* wq = reinterpret_cast<const float4*>(wt) + (kg * NCH) * 128 + j;
    const float* vv = vin + kg * (R / 4);
    float4 wp[DEPTH];
#pragma unroll
    for (int d = 0; d < DEPTH; d++) wp[d] = __ldg(wq + d * 128);
    float a = 0.f;
#pragma unroll
    for (int c = 0; c < NCH; c++) {
        const float4 wc = wp[c % DEPTH];
        if (c + DEPTH < NCH) wp[c % DEPTH] = __ldg(wq + (c + DEPTH) * 128);
        a = fmaf(vv[4*c+0], wc.x, a);
        a = fmaf(vv[4*c+1], wc.y, a);
        a = fmaf(vv[4*c+2], wc.z, a);
        a = fmaf(vv[4*c+3], wc.w, a);
    }
    if (kg > 0) pbuf[(kg - 1) * 128 + j] = a;
    __syncthreads();
    if (kg == 0) {
        float s = a;
        s += pbuf[j];
        s += pbuf[128 + j];
        s += pbuf[256 + j];
        s += __ldg(bias + j);
        if (ADD) out[j] += s; else out[j] = s;
    }
    __syncthreads();
}

// ---------------- encoder self-attention, kt-split (2 threads per head-token) ----------------
template<int S>
__device__ __forceinline__ void attnP(const float* __restrict__ q,
                                      const float* __restrict__ k,
                                      const float* __restrict__ v,
                                      float* __restrict__ ao, int qt0, int qt1)
{
    constexpr int H0 = (S + 1) / 2;
    const int items = 16 * (qt1 - qt0);
    for (int w = threadIdx.x; w < items; w += NTH) {
        const unsigned mask = __activemask();
        const int half = w & 1;
        const int head = (w >> 1) & 7;
        const int qt   = qt0 + (w >> 4);
        const int kbeg = half ? H0 : 0;
        const int kend = half ? S : H0;
        const float* qp = q + qt * QLD + head * 16;
        unsigned long long qq[8];
#pragma unroll
        for (int u = 0; u < 4; u++) {
            const ulonglong2 t = reinterpret_cast<const ulonglong2*>(qp)[u];
            qq[2*u] = t.x; qq[2*u+1] = t.y;
        }
        float sc[H0];
        float mx = -INFINITY;
#pragma unroll
        for (int i = 0; i < H0; i++) {
            const int kt = kbeg + i;
            const ulonglong2* kp =
                reinterpret_cast<const ulonglong2*>(k + kt * QLD + head * 16);
            unsigned long long acc = 0ull;
#pragma unroll
            for (int u = 0; u < 4; u++) {
                const ulonglong2 t = kp[u];
                asm("fma.rn.f32x2 %0, %1, %2, %0;" : "+l"(acc) : "l"(qq[2*u]),   "l"(t.x));
                asm("fma.rn.f32x2 %0, %1, %2, %0;" : "+l"(acc) : "l"(qq[2*u+1]), "l"(t.y));
            }
            float lo, hi;
            asm("mov.b64 {%0,%1}, %2;" : "=f"(lo), "=f"(hi) : "l"(acc));
            float s = (lo + hi) * 0.25f;
            if (kt >= kend) s = -INFINITY;   // pad slot (odd S, second half)
            sc[i] = s;
            mx = fmaxf(mx, s);
        }
        mx = fmaxf(mx, __shfl_xor_sync(mask, mx, 1));
        float ssum = 0.f;
#pragma unroll
        for (int i = 0; i < H0; i++) {
            const float e = __expf(sc[i] - mx);
            sc[i] = e;
            ssum += e;
        }
        ssum += __shfl_xor_sync(mask, ssum, 1);
        const float inv = 1.0f / ssum;
        unsigned long long ov[8];
#pragma unroll
        for (int u = 0; u < 8; u++) ov[u] = 0ull;
#pragma unroll
        for (int i = 0; i < H0; i++) {
            const int kt = kbeg + i;
            const float pv = sc[i] * inv;
            unsigned long long pv2;
            asm("mov.b64 %0,{%1,%1};" : "=l"(pv2) : "f"(pv));
            const ulonglong2* vp =
                reinterpret_cast<const ulonglong2*>(v + ((kt < S) ? kt : 0) * QLD + head * 16);
#pragma unroll
            for (int u = 0; u < 4; u++) {
                const ulonglong2 t = vp[u];
                asm("fma.rn.f32x2 %0, %1, %2, %0;" : "+l"(ov[2*u])   : "l"(t.x), "l"(pv2));
                asm("fma.rn.f32x2 %0, %1, %2, %0;" : "+l"(ov[2*u+1]) : "l"(t.y), "l"(pv2));
            }
        }
#pragma unroll
        for (int u = 0; u < 8; u++) {
            const unsigned long long o = __shfl_xor_sync(mask, ov[u], 1);
            asm("add.rn.f32x2 %0, %0, %1;" : "+l"(ov[u]) : "l"(o));
        }
        float* aop = ao + (qt >> 1) * 256 + (qt & 1) + 2 * head * 16;
        const int u0 = half * 4;
#pragma unroll
        for (int d = 0; d < 4; d++) {
            float lo, hi;
            asm("mov.b64 {%0,%1}, %2;" : "=f"(lo), "=f"(hi) : "l"(ov[u0 + d]));
            aop[4 * (u0 + d)]     = lo;
            aop[4 * (u0 + d) + 2] = hi;
        }
    }
}

// h (interleaved) = LN(h + ob(linear)) for tokens [t0, t1)
__device__ __forceinline__ void addln(float* __restrict__ h, const float* __restrict__ ob,
                                      const float* __restrict__ g, const float* __restrict__ bt,
                                      int t0, int t1)
{
    const int warp = threadIdx.x >> 5, lane = threadIdx.x & 31;
    for (int t = t0 + warp; t < t1; t += 16) {
        float* hp = h + (t >> 1) * 256 + (t & 1);
        const float* op = ob + t * 128;
        float r[4];
        float s = 0.f;
#pragma unroll
        for (int u = 0; u < 4; u++) {
            const int j = u * 32 + lane;
            r[u] = hp[2 * j] + op[j];
            s += r[u];
        }
#pragma unroll
        for (int off = 16; off; off >>= 1) s += __shfl_xor_sync(0xffffffffu, s, off);
        const float mu = s * (1.0f / 128.0f);
        float vs = 0.f;
#pragma unroll
        for (int u = 0; u < 4; u++) { const float d = r[u] - mu; vs = fmaf(d, d, vs); }
#pragma unroll
        for (int off = 16; off; off >>= 1) vs += __shfl_xor_sync(0xffffffffu, vs, off);
        const float rs = rsqrtf(vs * (1.0f / 128.0f) + 1e-5f);
#pragma unroll
        for (int u = 0; u < 4; u++) {
            const int j = u * 32 + lane;
            hp[2 * j] = fmaf(g[j] * (r[u] - mu), rs, bt[j]);
        }
    }
}

// token embedding for tokens [t0, t1); pads (state t>=37) zeroed
template<bool ACTION>
__device__ __forceinline__ void embed(float* __restrict__ h,
                                      const float* __restrict__ tcx,
                                      const float* __restrict__ tcy,
                                      const float* __restrict__ W,
                                      const float* __restrict__ b,
                                      int t0, int t1)
{
    const int total = (t1 - t0) * 128;
    for (int idx = threadIdx.x; idx < total; idx += NTH) {
        const int t = t0 + (idx >> 7), j = idx & 127;
        float val = 0.f;
        if (ACTION || t < SSQ) {
            const int c = ACTION ? (t < KA ? t : KS) : t;
            val = fmaf(tcx[c], __ldg(W + j), fmaf(tcy[c], __ldg(W + 128 + j), __ldg(b + j)));
        }
        h[(t >> 1) * 256 + 2 * j + (t & 1)] = val;
    }
}

// 2-layer encoder on own token rows; k,v peer-replicated for attention
template<int S, int PPGL, int PAIRB, int T0, int T1>
__device__ __forceinline__ void encode(float* __restrict__ h, float* __restrict__ scr,
                                       float* __restrict__ ob, float* __restrict__ wbuf,
                                       int attnOff, const float* attnB,
                                       int w1Off, const float* b1,
                                       int w2Off, const float* b2,
                                       const float* ln, uint32_t prank)
{
    float* q  = scr;
    float* k  = scr + 5280;    // 40 * QLD
    float* v  = scr + 10560;
    float* ao = ob;            // attention output shares ob buffer (gemmK in-place safe)
    const int oc128[4] = {128, 128, 128, 128};
    const int ocQKV[3] = {QLD, QLD, QLD};
    const int oc512[4] = {512, 512, 512, 512};
    const int ob0[4]   = {0, 0, 0, 0};
    const int obF[4]   = {0, 128, 256, 384};
#pragma unroll 1
    for (int l = 0; l < 2; l++) {
        const float* Wqkv = g_wt + attnOff + (l * 4 + 0) * 16384;
        const float* Wo   = g_wt + attnOff + (l * 4 + 3) * 16384;
        const float* biasQKV[3] = { attnB + (l * 4 + 0) * 128,
                                    attnB + (l * 4 + 1) * 128,
                                    attnB + (l * 4 + 2) * 128 };
        const float* biasO[1] = { attnB + (l * 4 + 3) * 128 };
        float* outQKV[3] = { q, k, v };
        float* outO[1]   = { ob };

        CLUSTER_SYNC();   // peer done reading its k,v copy; safe to overwrite via stPeer
        gemmF<PPGL, 128, 3, 4, false, true, 6>(h, Wqkv, biasQKV, outQKV, ob0, ocQKV,
                                               wbuf, PAIRB, prank);
        CLUSTER_SYNC();   // full k,v present in both CTAs
        attnP<S>(q, k, v, ao, T0, T1);
        __syncthreads();
        gemmK<4 * PPGL, 128, 1, false, 0>(ao, Wo, biasO, outO, ob0, oc128,
                                          wbuf, PAIRB, prank);
        addln(h, ob, ln + (l * 2 + 0) * 256, ln + (l * 2 + 0) * 256 + 128, T0, T1);
        __syncthreads();

        const float* W1b = g_wt + w1Off + l * 65536;
        const float* b1b = b1 + l * 512;
        const float* biasF1[4] = { b1b, b1b + 128, b1b + 256, b1b + 384 };
        float* outF1[4] = { scr, scr, scr, scr };
        gemmF<PPGL, 128, 4, 4, true, false, 0>(h, W1b, biasF1, outF1, obF, oc512,
                                               wbuf, PAIRB, prank);
        const float* biasF2[1] = { b2 + l * 128 };
        float* outF2[1] = { ob };
        gemmK<4 * PPGL, 512, 1, false, 0>(scr, g_wt + w2Off + l * 65536, biasF2,
                                          outF2, ob0, oc128, wbuf, PAIRB, prank);
        addln(h, ob, ln + (l * 2 + 1) * 256, ln + (l * 2 + 1) * 256 + 128, T0, T1);
        __syncthreads();
    }
}

extern __shared__ float sm[];

__global__ void __launch_bounds__(NTH, 1) __cluster_dims__(2, 1, 1) tsp_kernel(Params p)
{
    const int b = blockIdx.x >> 1, tid = threadIdx.x;
    const uint32_t rank = blockIdx.x & 1, prank = rank ^ 1;
    const int B = gridDim.x >> 1;

    float* xsx  = sm + O_XSX;
    float* xsy  = sm + O_XSY;
    float* h    = sm + O_H;
    float* scr  = sm + O_SCR;
    float* ob   = sm + O_OB;
    float* ea   = sm + O_EA;
    float* Kb   = sm + O_KB;
    float* Vb   = sm + O_VB;
    float* eq   = sm + O_EQ;
    float* hdec = sm + O_HDEC;
    float* q2   = sm + O_Q2;
    float* odec = sm + O_ODEC;
    float* sc   = sm + O_SCT;
    float* lg   = sm + O_LG;
    float* tcx  = sm + O_TCX;
    float* tcy  = sm + O_TCY;
    float* misc = sm + O_MISC;
    float* wbuf = sm + O_WBUF;
    int* knn   = (int*)(sm + O_INT);
    int* valid = knn + 35;
    int* mask  = knn + 50;

    for (int n = tid; n < NN; n += NTH) {
        xsx[n] = p.x[(b * NN + n) * 2 + 0];
        xsy[n] = p.x[(b * NN + n) * 2 + 1];
        mask[n] = 1;
    }
    __syncthreads();
    if (tid == 0) {
        const int st = p.start[b];
        mask[st] = 0;
        misc[0] = xsx[st]; misc[1] = xsy[st];
        misc[2] = xsx[st]; misc[3] = xsy[st];
        misc[4] = 0.f;
        if (rank == 0) p.out[b * NN] = (float)st;
    }
    __syncthreads();

    for (int step = 0; step < NN - 1; step++) {
        const float lastx = misc[0], lasty = misc[1];

        float* d2 = scr;
        if (tid < NN) {
            const float dx = xsx[tid] - lastx, dy = xsy[tid] - lasty;
            d2[tid] = mask[tid] ? (dx * dx + dy * dy) : 1e9f;
        }
        __syncthreads();

        // top-35 smallest (d2, idx), jax tie order — replicated in both CTAs
        if (tid < 32) {
            unsigned long long k0 = ~0ull, k1 = ~0ull;
            if (tid < NN)      k0 = (((unsigned long long)__float_as_uint(d2[tid]))      << 32) | (unsigned)tid;
            if (tid + 32 < NN) k1 = (((unsigned long long)__float_as_uint(d2[tid + 32])) << 32) | (unsigned)(tid + 32);
            for (int r = 0; r < KS; r++) {
                unsigned long long m = k0 < k1 ? k0 : k1;
#pragma unroll
                for (int off = 16; off; off >>= 1) {
                    unsigned long long o = __shfl_xor_sync(0xffffffffu, m, off);
                    if (o < m) m = o;
                }
                if (k0 == m) k0 = ~0ull;
                if (k1 == m) k1 = ~0ull;
                if (tid == 0) knn[r] = (int)(m & 0xffffffffull);
            }
        }
        __syncthreads();

        if (tid < KS) { const int n = knn[tid]; tcx[tid] = xsx[n]; tcy[tid] = xsy[n]; }
        if (tid < KA) valid[tid] = mask[knn[tid]];
        if (tid == 0) { tcx[35] = lastx; tcy[35] = lasty; tcx[36] = misc[2]; tcy[36] = misc[3]; }
        __syncthreads();

        // ---- ACTION encoder (16 tokens, 8/8 split) ----
        embed<true>(h, tcx, tcy, p.aEmbW, p.aEmbB, (int)rank * 8, (int)rank * 8 + 8);
        __syncthreads();
        if (rank == 0)
            encode<SAQ, 1, 0, 0, 8>(h, scr, ob, wbuf, OFF_AATTN, p.aAttnB,
                                    OFF_AW1, p.aB1, OFF_AW2, p.aB2, p.aLn, prank);
        else
            encode<SAQ, 1, 4, 8, 16>(h, scr, ob, wbuf, OFF_AATTN, p.aAttnB,
                                     OFF_AW1, p.aB1, OFF_AW2, p.aB2, p.aLn, prank);
        // copy own SA rows to ea
        for (int i = tid + (int)rank * 1024; i < 1024 + (int)rank * 1024; i += NTH) ea[i] = h[i];
        __syncthreads();

        // ---- STATE encoder (37 tokens: 24/13 split, pairs 12/8) ----
        embed<false>(h, tcx, tcy, p.sEmbW, p.sEmbB, rank ? 24 : 0, rank ? 40 : 24);
        __syncthreads();
        if (rank == 0)
            encode<SSQ, 3, 0, 0, 24>(h, scr, ob, wbuf, OFF_SATTN, p.sAttnB,
                                     OFF_SW1, p.sB1, OFF_SW2, p.sB2, p.sLn, prank);
        else
            encode<SSQ, 2, 12, 24, 37>(h, scr, ob, wbuf, OFF_SATTN, p.sAttnB,
                                       OFF_SW1, p.sB1, OFF_SW2, p.sB2, p.sLn, prank);

        // ---- exchange encoder outputs (64-bit packed DSMEM stores) ----
        {
            const unsigned long long* eaU = reinterpret_cast<const unsigned long long*>(ea);
            const unsigned long long* hU  = reinterpret_cast<const unsigned long long*>(h);
            if (rank == 0) {
                for (int i = tid; i < 512;  i += NTH) stPeer2(eaU + i, eaU[i], prank);
                for (int i = tid; i < 1024; i += NTH) stPeer2(hU + i, hU[i], prank);
            } else {
                for (int i = tid; i < 512; i += NTH) stPeer2(eaU + 512 + i, eaU[512 + i], prank);
                for (int i = tid; i < 256; i += NTH) stPeer2(hU + 2176 + i, hU[2176 + i], prank);
            }
        }
        CLUSTER_SYNC();

        // ---- eq = [ea row15 | h row35 | h row36] — replicated ----
        if (tid < 128) {
            eq[tid]       = ea[7 * 256 + 2 * tid + 1];
            eq[128 + tid] = h[17 * 256 + 2 * tid + 1];
            eq[256 + tid] = h[18 * 256 + 2 * tid + 0];
        }
        __syncthreads();

        // ---- h_dec = emb_q @ Wq_mlp + bq_mlp (K-split) ----
        matvecK<384, false>(eq, g_wt + OFF_WQM, p.bqm, hdec, wbuf);

        // ---- K (256 cols) & V (128 cols), fused K-split directly from ea/h ----
        {
            const float* biasKV[3] = { p.bK, p.bK + 128, p.bV };
            float* outKV[3] = { Kb, Kb, Vb };
            const int obKV[3] = { 0, 128, 0 };
            const int ocKV[3] = { 256, 256, 128 };
            gemmKV<4>(ea, h, g_wt + OFF_WK, biasKV, outKV, obKV, ocKV, wbuf,
                      (int)rank * 4, prank);
        }
        CLUSTER_SYNC();   // full Kb, Vb in both CTAs

        // ---- decoder layer 0 (replicated) ----
        matvecK<128, false>(hdec, g_wt + OFF_DWQ, p.dbq, q2, wbuf);
        if (tid < 120) {
            const int head = tid & 7, kk = tid >> 3;
            float s = 0.f;
            const float* kp = Kb + kk * 256 + head * 16;
#pragma unroll
            for (int d = 0; d < 16; d++) s = fmaf(q2[head * 16 + d], kp[d], s);
            s *= 0.25f;
            sc[head * 15 + kk] = valid[kk] ? s : -1e9f;
        }
        __syncthreads();
        if (tid < 8) {
            float mx = -INFINITY;
            for (int kk = 0; kk < KA; kk++) mx = fmaxf(mx, sc[tid * 15 + kk]);
            float ssum = 0.f;
            for (int kk = 0; kk < KA; kk++) {
                const float e = __expf(sc[tid * 15 + kk] - mx);
                sc[tid * 15 + kk] = e;
                ssum += e;
            }
            const float inv = 1.0f / ssum;
            for (int kk = 0; kk < KA; kk++) sc[tid * 15 + kk] *= inv;
        }
        __syncthreads();
        if (tid < 128) {
            const int head = tid >> 4, d = tid & 15;
            float o = 0.f;
            for (int kk = 0; kk < KA; kk++)
                o = fmaf(sc[head * 15 + kk], Vb[kk * 128 + head * 16 + d], o);
            odec[tid] = o;
        }
        __syncthreads();
        matvecK<128, true>(odec, g_wt + OFF_DWO, p.dbo, hdec, wbuf);

        // ---- final pointer layer ----
        matvecK<128, false>(hdec, g_wt + OFF_DWQ + 16384, p.dbq + 128, q2, wbuf);
        if (tid < 480) {
            const int w = tid >> 5, l = tid & 31;
            const float4 qv = *reinterpret_cast<const float4*>(q2 + 4 * l);
            const float4 kv = *reinterpret_cast<const float4*>(Kb + w * 256 + 128 + 4 * l);
            float s = 0.f;
            s = fmaf(qv.x, kv.x, s);
            s = fmaf(qv.y, kv.y, s);
            s = fmaf(qv.z, kv.z, s);
            s = fmaf(qv.w, kv.w, s);
#pragma unroll
            for (int off = 16; off; off >>= 1) s += __shfl_xor_sync(0xffffffffu, s, off);
            if (l == 0) {
                s *= 0.08838834764831845f;
                s = 10.0f * tanhf(s);
                lg[w] = valid[w] ? s : -1e9f;
            }
        }
        __syncthreads();
        if (tid == 0) {
            float mx = -INFINITY; int best = 0;
            for (int kk = 0; kk < KA; kk++)
                if (lg[kk] > mx) { mx = lg[kk]; best = kk; }
            float ssum = 0.f, eb = 0.f;
            for (int kk = 0; kk < KA; kk++) {
                const float e = __expf(lg[kk] - mx);
                ssum += e;
                if (kk == best) eb = e;
            }
            misc[4] += __logf(eb / ssum);
            const int nxt = knn[best];
            mask[nxt] = 0;
            misc[0] = xsx[nxt]; misc[1] = xsy[nxt];
            if (rank == 0) p.out[b * NN + step + 1] = (float)nxt;
        }
        __syncthreads();
    }

    if (rank == 0 && tid == 0) p.out[B * NN + b] = misc[4];
    CLUSTER_SYNC();
}

extern "C" void kernel_launch(void* const* d_in, const int* in_sizes, int n_in,
                              void* d_out, int out_size)
{
    int i = 2;
    if (n_in > 2 && in_sizes[2] == 1) i = 4;

    TQJobs jb;
    const float* srcs[11] = {
        (const float*)d_in[i+2],   // aAttnW
        (const float*)d_in[i+11],  // sAttnW
        (const float*)d_in[i+4],   // aW1
        (const float*)d_in[i+13],  // sW1
        (const float*)d_in[i+6],   // aW2
        (const float*)d_in[i+15],  // sW2
        (const float*)d_in[i+18],  // WK
        (const float*)d_in[i+20],  // WV
        (const float*)d_in[i+22],  // Wqm
        (const float*)d_in[i+24],  // dWq
        (const float*)d_in[i+26],  // dWo
    };
    const int offs[11]  = {OFF_AATTN, OFF_SATTN, OFF_AW1, OFF_SW1, OFF_AW2, OFF_SW2,
                           OFF_WK, OFF_WV, OFF_WQM, OFF_DWQ, OFF_DWO};
    const int Rs[11]    = {128, 128, 128, 128, 512, 512, 256, 256, 384, 128, 128};
    const int Cs[11]    = {128, 128, 512, 512, 128, 128, 256, 256, 128, 128, 128};
    const int nms[11]   = {8, 8, 2, 2, 2, 2, 1, 1, 1, 2, 2};
    for (int s = 0; s < 11; s++) {
        jb.src[s] = srcs[s]; jb.dstOff[s] = offs[s];
        jb.R[s] = Rs[s]; jb.C[s] = Cs[s]; jb.nmat[s] = nms[s];
    }
    tq_all<<<128, 256>>>(jb);

    Params p;
    p.x = (const float*)d_in[0];
    p.start = (const int*)d_in[1];
    p.aEmbW = (const float*)d_in[i+0];  p.aEmbB = (const float*)d_in[i+1];
    p.aAttnB = (const float*)d_in[i+3];
    p.aB1 = (const float*)d_in[i+5];    p.aB2 = (const float*)d_in[i+7];
    p.aLn = (const float*)d_in[i+8];
    p.sEmbW = (const float*)d_in[i+9];  p.sEmbB = (const float*)d_in[i+10];
    p.sAttnB = (const float*)d_in[i+12];
    p.sB1 = (const float*)d_in[i+14];   p.sB2 = (const float*)d_in[i+16];
    p.sLn = (const float*)d_in[i+17];
    p.bK  = (const float*)d_in[i+19];
    p.bV  = (const float*)d_in[i+21];
    p.bqm = (const float*)d_in[i+23];
    p.dbq = (const float*)d_in[i+25];
    p.dbo = (const float*)d_in[i+27];
    p.out = (float*)d_out;

    cudaFuncSetAttribute(tsp_kernel, cudaFuncAttributeMaxDynamicSharedMemorySize, SMEM_BYTES);

    const int B = in_sizes[1];
    tsp_kernel<<<2 * B, NTH, SMEM_BYTES>>>(p);
}

// round 17
// speedup vs baseline: 1.1061x; 1.0223x over previous
#include <cuda_runtime.h>
#include <math.h>
#include <stdint.h>

#define NTH 512
#define NN  50
#define KA  15
#define KS  35
#define SAQ 16
#define SSQ 37
#define QLD 132   // q/k/v row stride (floats): bank-conflict-free attention

// ------------- transposed weight scratch (block-contiguous quad layout) -------------
#define OFF_AATTN 0
#define OFF_SATTN 131072
#define OFF_AW1   262144
#define OFF_SW1   393216
#define OFF_AW2   524288
#define OFF_SW2   655360
#define OFF_WK    786432
#define OFF_WV    851968
#define OFF_WQM   917504
#define OFF_DWQ   966656
#define OFF_DWO   999424
#define WT_TOTAL  1032192

__device__ float g_wt[WT_TOTAL];

// ---------------- shared memory layout (float offsets) ----------------
#define O_XSX  0
#define O_XSY  64
#define O_H    128        // 40x128 interleaved = 5120
#define O_SCR  5248       // 20480: q@0,k@5280,v@10560 (stride 132); FF1; d2
#define O_OB   25728      // 5120 (also holds attention output ao, interleaved)
#define O_EA   30848      // 2048
#define O_KB   32896      // 4096
#define O_VB   36992      // 2048
#define O_EQ   39040      // 384
#define O_HDEC 39424
#define O_Q2   39552
#define O_ODEC 39680
#define O_SCT  39808
#define O_LG   39936
#define O_TCX  39952
#define O_TCY  39992
#define O_MISC 40032
#define O_INT  40040      // ints
#define O_WBUF 40144      // 16384 floats (64KB): gemmF staging / gemmK & matvecK partials
#define SMEM_FLOATS 56528
#define SMEM_BYTES (SMEM_FLOATS * 4)

struct Params {
    const float* x; const int* start;
    const float *aEmbW, *aEmbB, *aAttnB, *aB1, *aB2, *aLn;
    const float *sEmbW, *sEmbB, *sAttnB, *sB1, *sB2, *sLn;
    const float *bK, *bV, *bqm, *dbq, *dbo;
    float* out;
};

// ---------------- cluster helpers ----------------
__device__ __forceinline__ uint32_t smaddr(const void* p){
    uint32_t a;
    asm("{ .reg .u64 t; cvta.to.shared.u64 t, %1; cvt.u32.u64 %0, t; }" : "=r"(a) : "l"(p));
    return a;
}
__device__ __forceinline__ void stPeer(const void* lp, float v, uint32_t prank){
    uint32_t l = smaddr(lp), r;
    asm("mapa.shared::cluster.u32 %0, %1, %2;" : "=r"(r) : "r"(l), "r"(prank));
    asm volatile("st.shared::cluster.f32 [%0], %1;" :: "r"(r), "f"(v) : "memory");
}
__device__ __forceinline__ void stPeer2(const void* lp, unsigned long long v, uint32_t prank){
    uint32_t l = smaddr(lp), r;
    asm("mapa.shared::cluster.u32 %0, %1, %2;" : "=r"(r) : "r"(l), "r"(prank));
    asm volatile("st.shared::cluster.b64 [%0], %1;" :: "r"(r), "l"(v) : "memory");
}
#define CLUSTER_SYNC() do { \
    asm volatile("barrier.cluster.arrive.aligned;" ::: "memory"); \
    asm volatile("barrier.cluster.wait.aligned;" ::: "memory"); } while(0)

// ---------------- merged weight-transpose prologue ----------------
struct TQJobs {
    const float* src[11];
    int dstOff[11], R[11], C[11], nmat[11];
};

__global__ void tq_all(TQJobs jb)
{
#pragma unroll 1
    for (int s = 0; s < 11; s++) {
        const int R = jb.R[s], C = jb.C[s];
        const int total = jb.nmat[s] * R * C;
        const float* __restrict__ src = jb.src[s];
        const int dstOff = jb.dstOff[s];
        for (int idx = blockIdx.x * blockDim.x + threadIdx.x; idx < total;
             idx += gridDim.x * blockDim.x) {
            const int m = idx / (R * C);
            const int rem = idx - m * R * C;
            const int r = rem / C;
            const int c = rem - r * C;
            g_wt[dstOff + m * R * C + (c >> 7) * (R * 128)
                 + ((r >> 2) << 9) + ((c & 127) << 2) + (r & 3)] = src[idx];
        }
    }
}

// ---------------- fused multi-block smem-staged packed-f32x2 GEMM ----------------
template<int PPG, int DIN, int NBLK, int TC, bool RELU, bool LINOUT, int PEERMASK>
__device__ __forceinline__ void gemmF(const float* __restrict__ in,
                                      const float* __restrict__ wt,
                                      const float* const* bias,
                                      float* const* outp,
                                      const int* obase,
                                      const int* ocols,
                                      float* __restrict__ wbuf,
                                      int pairBase, uint32_t prank)
{
    constexpr int T    = DIN / (4 * TC);
    constexpr int BUF4 = NBLK * TC * 128;
    constexpr int F4PT = BUF4 / NTH;
    const int j = threadIdx.x & 127;
    const int g = threadIdx.x >> 7;
    const float* inb = in + (pairBase + g * PPG) * 2 * DIN;
    const float4* wg4 = reinterpret_cast<const float4*>(wt);
    float4* wb4 = reinterpret_cast<float4*>(wbuf);

    float4 pre[F4PT];
#pragma unroll
    for (int s = 0; s < F4PT; s++) {
        const int idx = threadIdx.x + s * NTH;
        const int bk = idx / (TC * 128);
        const int rem = idx - bk * (TC * 128);
        pre[s] = __ldg(wg4 + bk * (DIN * 32) + rem);
    }
    unsigned long long acc[NBLK][PPG];
#pragma unroll
    for (int bk = 0; bk < NBLK; bk++)
#pragma unroll
        for (int p = 0; p < PPG; p++) acc[bk][p] = 0ull;

#pragma unroll 1
    for (int t = 0; t < T; t++) {
        float4* wb = wb4 + (t & 1) * BUF4;
#pragma unroll
        for (int s = 0; s < F4PT; s++) wb[threadIdx.x + s * NTH] = pre[s];
        __syncthreads();
        if (t + 1 < T) {
#pragma unroll
            for (int s = 0; s < F4PT; s++) {
                const int idx = threadIdx.x + s * NTH;
                const int bk = idx / (TC * 128);
                const int rem = idx - bk * (TC * 128);
                pre[s] = __ldg(wg4 + bk * (DIN * 32) + (t + 1) * (TC * 128) + rem);
            }
        }
#pragma unroll
        for (int ci = 0; ci < TC; ci++) {
            const int kk = t * TC + ci;
            ulonglong2 a01[PPG], a23[PPG];
#pragma unroll
            for (int p = 0; p < PPG; p++) {
                const ulonglong2* ip =
                    reinterpret_cast<const ulonglong2*>(inb + p * 2 * DIN + 8 * kk);
                a01[p] = ip[0];
                a23[p] = ip[1];
            }
#pragma unroll
            for (int bk = 0; bk < NBLK; bk++) {
                const float4 w = wb[bk * (TC * 128) + ci * 128 + j];
                unsigned long long w0, w1, w2, w3;
                asm("mov.b64 %0,{%1,%1};" : "=l"(w0) : "f"(w.x));
                asm("mov.b64 %0,{%1,%1};" : "=l"(w1) : "f"(w.y));
                asm("mov.b64 %0,{%1,%1};" : "=l"(w2) : "f"(w.z));
                asm("mov.b64 %0,{%1,%1};" : "=l"(w3) : "f"(w.w));
#pragma unroll
                for (int p = 0; p < PPG; p++) {
                    asm("fma.rn.f32x2 %0, %1, %2, %0;" : "+l"(acc[bk][p]) : "l"(a01[p].x), "l"(w0));
                    asm("fma.rn.f32x2 %0, %1, %2, %0;" : "+l"(acc[bk][p]) : "l"(a01[p].y), "l"(w1));
                    asm("fma.rn.f32x2 %0, %1, %2, %0;" : "+l"(acc[bk][p]) : "l"(a23[p].x), "l"(w2));
                    asm("fma.rn.f32x2 %0, %1, %2, %0;" : "+l"(acc[bk][p]) : "l"(a23[p].y), "l"(w3));
                }
            }
        }
    }
#pragma unroll
    for (int bk = 0; bk < NBLK; bk++) {
        const float bb = __ldg(bias[bk] + j);
#pragma unroll
        for (int p = 0; p < PPG; p++) {
            float lo, hi;
            asm("mov.b64 {%0,%1}, %2;" : "=f"(lo), "=f"(hi) : "l"(acc[bk][p]));
            lo += bb; hi += bb;
            if (RELU) { lo = fmaxf(lo, 0.f); hi = fmaxf(hi, 0.f); }
            const int pr = pairBase + g * PPG + p;
            if (LINOUT) {
                float* o0 = outp[bk] + (2 * pr + 0) * ocols[bk] + obase[bk] + j;
                float* o1 = outp[bk] + (2 * pr + 1) * ocols[bk] + obase[bk] + j;
                *o0 = lo; *o1 = hi;
                if (PEERMASK & (1 << bk)) { stPeer(o0, lo, prank); stPeer(o1, hi, prank); }
            } else {
                *reinterpret_cast<float2*>(outp[bk] + pr * 2 * ocols[bk]
                                           + 2 * (obase[bk] + j)) = make_float2(lo, hi);
            }
        }
    }
    __syncthreads();
}

// ---------------- K-split packed-f32x2 GEMM (direct-LDG weights, depth-4 prefetch) ----------------
template<int LP, int DIN, int NBLK, bool RELU, int PEERMASK>
__device__ __forceinline__ void gemmK(const float* __restrict__ in,
                                      const float* __restrict__ wt,
                                      const float* const* bias,
                                      float* const* outp,
                                      const int* obase,
                                      const int* ocols,
                                      float* __restrict__ wbuf,
                                      int pairBase, uint32_t prank)
{
    constexpr int NCH = DIN / 16;
    constexpr int DEPTH = (NCH < 4) ? NCH : 4;
    const int j  = threadIdx.x & 127;
    const int kg = threadIdx.x >> 7;
    const float* inb = in + pairBase * 2 * DIN;
    const float4* wq = reinterpret_cast<const float4*>(wt) + (kg * NCH) * 128 + j;

    unsigned long long acc[NBLK][LP];
#pragma unroll
    for (int bk = 0; bk < NBLK; bk++)
#pragma unroll
        for (int p = 0; p < LP; p++) acc[bk][p] = 0ull;

    float4 wp[NBLK][DEPTH];
#pragma unroll
    for (int bk = 0; bk < NBLK; bk++)
#pragma unroll
        for (int d = 0; d < DEPTH; d++)
            wp[bk][d] = __ldg(wq + bk * (DIN * 32) + d * 128);
#pragma unroll 4
    for (int c = 0; c < NCH; c++) {
        unsigned long long w[NBLK][4];
#pragma unroll
        for (int bk = 0; bk < NBLK; bk++) {
            const float4 wc = wp[bk][c % DEPTH];
            if (c + DEPTH < NCH)
                wp[bk][c % DEPTH] = __ldg(wq + bk * (DIN * 32) + (c + DEPTH) * 128);
            asm("mov.b64 %0,{%1,%1};" : "=l"(w[bk][0]) : "f"(wc.x));
            asm("mov.b64 %0,{%1,%1};" : "=l"(w[bk][1]) : "f"(wc.y));
            asm("mov.b64 %0,{%1,%1};" : "=l"(w[bk][2]) : "f"(wc.z));
            asm("mov.b64 %0,{%1,%1};" : "=l"(w[bk][3]) : "f"(wc.w));
        }
        const int kk = kg * NCH + c;
#pragma unroll
        for (int p = 0; p < LP; p++) {
            const ulonglong2* ip =
                reinterpret_cast<const ulonglong2*>(inb + p * 2 * DIN + 8 * kk);
            const ulonglong2 a01 = ip[0];
            const ulonglong2 a23 = ip[1];
#pragma unroll
            for (int bk = 0; bk < NBLK; bk++) {
                asm("fma.rn.f32x2 %0, %1, %2, %0;" : "+l"(acc[bk][p]) : "l"(a01.x), "l"(w[bk][0]));
                asm("fma.rn.f32x2 %0, %1, %2, %0;" : "+l"(acc[bk][p]) : "l"(a01.y), "l"(w[bk][1]));
                asm("fma.rn.f32x2 %0, %1, %2, %0;" : "+l"(acc[bk][p]) : "l"(a23.x), "l"(w[bk][2]));
                asm("fma.rn.f32x2 %0, %1, %2, %0;" : "+l"(acc[bk][p]) : "l"(a23.y), "l"(w[bk][3]));
            }
        }
    }

    if (kg > 0) {
#pragma unroll
        for (int bk = 0; bk < NBLK; bk++)
#pragma unroll
            for (int p = 0; p < LP; p++)
                *reinterpret_cast<unsigned long long*>(
                    wbuf + (((kg - 1) * NBLK + bk) * LP + p) * 256 + 2 * j) = acc[bk][p];
    }
    __syncthreads();
    if (kg == 0) {
#pragma unroll
        for (int bk = 0; bk < NBLK; bk++) {
            const float bb = __ldg(bias[bk] + j);
#pragma unroll
            for (int p = 0; p < LP; p++) {
                float lo, hi;
                asm("mov.b64 {%0,%1}, %2;" : "=f"(lo), "=f"(hi) : "l"(acc[bk][p]));
#pragma unroll
                for (int q = 0; q < 3; q++) {
                    const float2 t = *reinterpret_cast<const float2*>(
                        wbuf + ((q * NBLK + bk) * LP + p) * 256 + 2 * j);
                    lo += t.x; hi += t.y;
                }
                lo += bb; hi += bb;
                if (RELU) { lo = fmaxf(lo, 0.f); hi = fmaxf(hi, 0.f); }
                const int pr = pairBase + p;
                float* o0 = outp[bk] + (2 * pr + 0) * ocols[bk] + obase[bk] + j;
                float* o1 = outp[bk] + (2 * pr + 1) * ocols[bk] + obase[bk] + j;
                *o0 = lo; *o1 = hi;
                if (PEERMASK & (1 << bk)) { stPeer(o0, lo, prank); stPeer(o1, hi, prank); }
            }
        }
    }
    __syncthreads();
}

// ---------------- fused decoder K/V GEMM reading directly from ea/h ----------------
template<int LP>
__device__ __forceinline__ void gemmKV(const float* __restrict__ ea,
                                       const float* __restrict__ hh,
                                       const float* __restrict__ wt,
                                       const float* const* bias,
                                       float* const* outp,
                                       const int* obase,
                                       const int* ocols,
                                       float* __restrict__ wbuf,
                                       int pairBase, uint32_t prank)
{
    constexpr int DIN = 256, NBLK = 3;
    constexpr int NCH = DIN / 16;
    const int j  = threadIdx.x & 127;
    const int kg = threadIdx.x >> 7;
    const float4* wq = reinterpret_cast<const float4*>(wt) + (kg * NCH) * 128 + j;

    unsigned long long acc[NBLK][LP];
#pragma unroll
    for (int bk = 0; bk < NBLK; bk++)
#pragma unroll
        for (int p = 0; p < LP; p++) acc[bk][p] = 0ull;

    float4 wc[NBLK], wn[NBLK];
#pragma unroll
    for (int bk = 0; bk < NBLK; bk++) wc[bk] = __ldg(wq + bk * (DIN * 32));
#pragma unroll 1
    for (int c = 0; c < NCH; c++) {
        if (c + 1 < NCH) {
#pragma unroll
            for (int bk = 0; bk < NBLK; bk++)
                wn[bk] = __ldg(wq + bk * (DIN * 32) + (c + 1) * 128);
        }
        unsigned long long w[NBLK][4];
#pragma unroll
        for (int bk = 0; bk < NBLK; bk++) {
            asm("mov.b64 %0,{%1,%1};" : "=l"(w[bk][0]) : "f"(wc[bk].x));
            asm("mov.b64 %0,{%1,%1};" : "=l"(w[bk][1]) : "f"(wc[bk].y));
            asm("mov.b64 %0,{%1,%1};" : "=l"(w[bk][2]) : "f"(wc[bk].z));
            asm("mov.b64 %0,{%1,%1};" : "=l"(w[bk][3]) : "f"(wc[bk].w));
        }
        const int kk = kg * NCH + c;
        const float* src = (kk < 32) ? (ea + 8 * kk) : (hh + 8 * (kk - 32));
#pragma unroll
        for (int p = 0; p < LP; p++) {
            const ulonglong2* ip =
                reinterpret_cast<const ulonglong2*>(src + (pairBase + p) * 256);
            const ulonglong2 a01 = ip[0];
            const ulonglong2 a23 = ip[1];
#pragma unroll
            for (int bk = 0; bk < NBLK; bk++) {
                asm("fma.rn.f32x2 %0, %1, %2, %0;" : "+l"(acc[bk][p]) : "l"(a01.x), "l"(w[bk][0]));
                asm("fma.rn.f32x2 %0, %1, %2, %0;" : "+l"(acc[bk][p]) : "l"(a01.y), "l"(w[bk][1]));
                asm("fma.rn.f32x2 %0, %1, %2, %0;" : "+l"(acc[bk][p]) : "l"(a23.x), "l"(w[bk][2]));
                asm("fma.rn.f32x2 %0, %1, %2, %0;" : "+l"(acc[bk][p]) : "l"(a23.y), "l"(w[bk][3]));
            }
        }
#pragma unroll
        for (int bk = 0; bk < NBLK; bk++) wc[bk] = wn[bk];
    }

    if (kg > 0) {
#pragma unroll
        for (int bk = 0; bk < NBLK; bk++)
#pragma unroll
            for (int p = 0; p < LP; p++)
                *reinterpret_cast<unsigned long long*>(
                    wbuf + (((kg - 1) * NBLK + bk) * LP + p) * 256 + 2 * j) = acc[bk][p];
    }
    __syncthreads();
    if (kg == 0) {
#pragma unroll
        for (int bk = 0; bk < NBLK; bk++) {
            const float bb = __ldg(bias[bk] + j);
#pragma unroll
            for (int p = 0; p < LP; p++) {
                float lo, hi;
                asm("mov.b64 {%0,%1}, %2;" : "=f"(lo), "=f"(hi) : "l"(acc[bk][p]));
#pragma unroll
                for (int q = 0; q < 3; q++) {
                    const float2 t = *reinterpret_cast<const float2*>(
                        wbuf + ((q * NBLK + bk) * LP + p) * 256 + 2 * j);
                    lo += t.x; hi += t.y;
                }
                lo += bb; hi += bb;
                const int pr = pairBase + p;
                float* o0 = outp[bk] + (2 * pr + 0) * ocols[bk] + obase[bk] + j;
                float* o1 = outp[bk] + (2 * pr + 1) * ocols[bk] + obase[bk] + j;
                *o0 = lo; *o1 = hi;
                stPeer(o0, lo, prank); stPeer(o1, hi, prank);
            }
        }
    }
    __syncthreads();
}

// ---------------- K-split matvec with deep (8) weight prefetch ----------------
template<int R, bool ADD>
__device__ __forceinline__ void matvecK(const float* __restrict__ vin,
                                        const float* __restrict__ wt,
                                        const float* __restrict__ bias,
                                        float* __restrict__ out,
                                        float* __restrict__ pbuf)
{
    constexpr int NCH = R / 16;
    constexpr int DEPTH = (NCH < 8) ? NCH : 8;
    const int j  = threadIdx.x & 127;
    const int kg = threadIdx.x >> 7;
    const float4* wq = reinterpret_cast<const float4*>(wt) + (kg * NCH) * 128 + j;
    const float* vv = vin + kg * (R / 4);
    float4 wp[DEPTH];
#pragma unroll
    for (int d = 0; d < DEPTH; d++) wp[d] = __ldg(wq + d * 128);
    float a = 0.f;
#pragma unroll
    for (int c = 0; c < NCH; c++) {
        const float4 wc = wp[c % DEPTH];
        if (c + DEPTH < NCH) wp[c % DEPTH] = __ldg(wq + (c + DEPTH) * 128);
        a = fmaf(vv[4*c+0], wc.x, a);
        a = fmaf(vv[4*c+1], wc.y, a);
        a = fmaf(vv[4*c+2], wc.z, a);
        a = fmaf(vv[4*c+3], wc.w, a);
    }
    if (kg > 0) pbuf[(kg - 1) * 128 + j] = a;
    __syncthreads();
    if (kg == 0) {
        float s = a;
        s += pbuf[j];
        s += pbuf[128 + j];
        s += pbuf[256 + j];
        s += __ldg(bias + j);
        if (ADD) out[j] += s; else out[j] = s;
    }
    __syncthreads();
}

// ---------------- encoder self-attention, kt-split (2 threads per head-token) ----------------
template<int S>
__device__ __forceinline__ void attnP(const float* __restrict__ q,
                                      const float* __restrict__ k,
                                      const float* __restrict__ v,
                                      float* __restrict__ ao, int qt0, int qt1)
{
    constexpr int H0 = (S + 1) / 2;
    const int items = 16 * (qt1 - qt0);
    for (int w = threadIdx.x; w < items; w += NTH) {
        const unsigned mask = __activemask();
        const int half = w & 1;
        const int head = (w >> 1) & 7;
        const int qt   = qt0 + (w >> 4);
        const int kbeg = half ? H0 : 0;
        const int kend = half ? S : H0;
        const float* qp = q + qt * QLD + head * 16;
        unsigned long long qq[8];
#pragma unroll
        for (int u = 0; u < 4; u++) {
            const ulonglong2 t = reinterpret_cast<const ulonglong2*>(qp)[u];
            qq[2*u] = t.x; qq[2*u+1] = t.y;
        }
        float sc[H0];
        float mx = -INFINITY;
#pragma unroll
        for (int i = 0; i < H0; i++) {
            const int kt = kbeg + i;
            const ulonglong2* kp =
                reinterpret_cast<const ulonglong2*>(k + kt * QLD + head * 16);
            unsigned long long acc = 0ull;
#pragma unroll
            for (int u = 0; u < 4; u++) {
                const ulonglong2 t = kp[u];
                asm("fma.rn.f32x2 %0, %1, %2, %0;" : "+l"(acc) : "l"(qq[2*u]),   "l"(t.x));
                asm("fma.rn.f32x2 %0, %1, %2, %0;" : "+l"(acc) : "l"(qq[2*u+1]), "l"(t.y));
            }
            float lo, hi;
            asm("mov.b64 {%0,%1}, %2;" : "=f"(lo), "=f"(hi) : "l"(acc));
            float s = (lo + hi) * 0.25f;
            if (kt >= kend) s = -INFINITY;
            sc[i] = s;
            mx = fmaxf(mx, s);
        }
        mx = fmaxf(mx, __shfl_xor_sync(mask, mx, 1));
        float ssum = 0.f;
#pragma unroll
        for (int i = 0; i < H0; i++) {
            const float e = __expf(sc[i] - mx);
            sc[i] = e;
            ssum += e;
        }
        ssum += __shfl_xor_sync(mask, ssum, 1);
        const float inv = 1.0f / ssum;
        unsigned long long ov[8];
#pragma unroll
        for (int u = 0; u < 8; u++) ov[u] = 0ull;
#pragma unroll
        for (int i = 0; i < H0; i++) {
            const int kt = kbeg + i;
            const float pv = sc[i] * inv;
            unsigned long long pv2;
            asm("mov.b64 %0,{%1,%1};" : "=l"(pv2) : "f"(pv));
            const ulonglong2* vp =
                reinterpret_cast<const ulonglong2*>(v + ((kt < S) ? kt : 0) * QLD + head * 16);
#pragma unroll
            for (int u = 0; u < 4; u++) {
                const ulonglong2 t = vp[u];
                asm("fma.rn.f32x2 %0, %1, %2, %0;" : "+l"(ov[2*u])   : "l"(t.x), "l"(pv2));
                asm("fma.rn.f32x2 %0, %1, %2, %0;" : "+l"(ov[2*u+1]) : "l"(t.y), "l"(pv2));
            }
        }
#pragma unroll
        for (int u = 0; u < 8; u++) {
            const unsigned long long o = __shfl_xor_sync(mask, ov[u], 1);
            asm("add.rn.f32x2 %0, %0, %1;" : "+l"(ov[u]) : "l"(o));
        }
        float* aop = ao + (qt >> 1) * 256 + (qt & 1) + 2 * head * 16;
        const int u0 = half * 4;
#pragma unroll
        for (int d = 0; d < 4; d++) {
            float lo, hi;
            asm("mov.b64 {%0,%1}, %2;" : "=f"(lo), "=f"(hi) : "l"(ov[u0 + d]));
            aop[4 * (u0 + d)]     = lo;
            aop[4 * (u0 + d) + 2] = hi;
        }
    }
}

// h (interleaved) = LN(h + ob(linear)) for tokens [t0, t1)
__device__ __forceinline__ void addln(float* __restrict__ h, const float* __restrict__ ob,
                                      const float* __restrict__ g, const float* __restrict__ bt,
                                      int t0, int t1)
{
    const int warp = threadIdx.x >> 5, lane = threadIdx.x & 31;
    for (int t = t0 + warp; t < t1; t += 16) {
        float* hp = h + (t >> 1) * 256 + (t & 1);
        const float* op = ob + t * 128;
        float r[4];
        float s = 0.f;
#pragma unroll
        for (int u = 0; u < 4; u++) {
            const int j = u * 32 + lane;
            r[u] = hp[2 * j] + op[j];
            s += r[u];
        }
#pragma unroll
        for (int off = 16; off; off >>= 1) s += __shfl_xor_sync(0xffffffffu, s, off);
        const float mu = s * (1.0f / 128.0f);
        float vs = 0.f;
#pragma unroll
        for (int u = 0; u < 4; u++) { const float d = r[u] - mu; vs = fmaf(d, d, vs); }
#pragma unroll
        for (int off = 16; off; off >>= 1) vs += __shfl_xor_sync(0xffffffffu, vs, off);
        const float rs = rsqrtf(vs * (1.0f / 128.0f) + 1e-5f);
#pragma unroll
        for (int u = 0; u < 4; u++) {
            const int j = u * 32 + lane;
            hp[2 * j] = fmaf(g[j] * (r[u] - mu), rs, bt[j]);
        }
    }
}

// token embedding for tokens [t0, t1); pads (state t>=37) zeroed
template<bool ACTION>
__device__ __forceinline__ void embed(float* __restrict__ h,
                                      const float* __restrict__ tcx,
                                      const float* __restrict__ tcy,
                                      const float* __restrict__ W,
                                      const float* __restrict__ b,
                                      int t0, int t1)
{
    const int total = (t1 - t0) * 128;
    for (int idx = threadIdx.x; idx < total; idx += NTH) {
        const int t = t0 + (idx >> 7), j = idx & 127;
        float val = 0.f;
        if (ACTION || t < SSQ) {
            const int c = ACTION ? (t < KA ? t : KS) : t;
            val = fmaf(tcx[c], __ldg(W + j), fmaf(tcy[c], __ldg(W + 128 + j), __ldg(b + j)));
        }
        h[(t >> 1) * 256 + 2 * j + (t & 1)] = val;
    }
}

// 2-layer encoder on own token rows; k,v peer-replicated for attention
// SYNC0: emit the leading CLUSTER_SYNC for layer 0 (skippable when a prior
// cluster sync already fences the peer's last k/v read).
template<int S, int PPGL, int PAIRB, int T0, int T1, bool SYNC0>
__device__ __forceinline__ void encode(float* __restrict__ h, float* __restrict__ scr,
                                       float* __restrict__ ob, float* __restrict__ wbuf,
                                       int attnOff, const float* attnB,
                                       int w1Off, const float* b1,
                                       int w2Off, const float* b2,
                                       const float* ln, uint32_t prank)
{
    float* q  = scr;
    float* k  = scr + 5280;    // 40 * QLD
    float* v  = scr + 10560;
    float* ao = ob;            // attention output shares ob buffer (gemmK in-place safe)
    const int oc128[4] = {128, 128, 128, 128};
    const int ocQKV[3] = {QLD, QLD, QLD};
    const int oc512[4] = {512, 512, 512, 512};
    const int ob0[4]   = {0, 0, 0, 0};
    const int obF[4]   = {0, 128, 256, 384};
#pragma unroll 1
    for (int l = 0; l < 2; l++) {
        const float* Wqkv = g_wt + attnOff + (l * 4 + 0) * 16384;
        const float* Wo   = g_wt + attnOff + (l * 4 + 3) * 16384;
        const float* biasQKV[3] = { attnB + (l * 4 + 0) * 128,
                                    attnB + (l * 4 + 1) * 128,
                                    attnB + (l * 4 + 2) * 128 };
        const float* biasO[1] = { attnB + (l * 4 + 3) * 128 };
        float* outQKV[3] = { q, k, v };
        float* outO[1]   = { ob };

        if (SYNC0 || l > 0) CLUSTER_SYNC();   // peer done reading its k,v copy
        gemmF<PPGL, 128, 3, 4, false, true, 6>(h, Wqkv, biasQKV, outQKV, ob0, ocQKV,
                                               wbuf, PAIRB, prank);
        CLUSTER_SYNC();   // full k,v present in both CTAs
        attnP<S>(q, k, v, ao, T0, T1);
        __syncthreads();
        gemmK<4 * PPGL, 128, 1, false, 0>(ao, Wo, biasO, outO, ob0, oc128,
                                          wbuf, PAIRB, prank);
        addln(h, ob, ln + (l * 2 + 0) * 256, ln + (l * 2 + 0) * 256 + 128, T0, T1);
        __syncthreads();

        const float* W1b = g_wt + w1Off + l * 65536;
        const float* b1b = b1 + l * 512;
        const float* biasF1[4] = { b1b, b1b + 128, b1b + 256, b1b + 384 };
        float* outF1[4] = { scr, scr, scr, scr };
        gemmF<PPGL, 128, 4, 4, true, false, 0>(h, W1b, biasF1, outF1, obF, oc512,
                                               wbuf, PAIRB, prank);
        const float* biasF2[1] = { b2 + l * 128 };
        float* outF2[1] = { ob };
        gemmK<4 * PPGL, 512, 1, false, 0>(scr, g_wt + w2Off + l * 65536, biasF2,
                                          outF2, ob0, oc128, wbuf, PAIRB, prank);
        addln(h, ob, ln + (l * 2 + 1) * 256, ln + (l * 2 + 1) * 256 + 128, T0, T1);
        __syncthreads();
    }
}

extern __shared__ float sm[];

__global__ void __launch_bounds__(NTH, 1) __cluster_dims__(2, 1, 1) tsp_kernel(Params p)
{
    const int b = blockIdx.x >> 1, tid = threadIdx.x;
    const uint32_t rank = blockIdx.x & 1, prank = rank ^ 1;
    const int B = gridDim.x >> 1;

    float* xsx  = sm + O_XSX;
    float* xsy  = sm + O_XSY;
    float* h    = sm + O_H;
    float* scr  = sm + O_SCR;
    float* ob   = sm + O_OB;
    float* ea   = sm + O_EA;
    float* Kb   = sm + O_KB;
    float* Vb   = sm + O_VB;
    float* eq   = sm + O_EQ;
    float* hdec = sm + O_HDEC;
    float* q2   = sm + O_Q2;
    float* odec = sm + O_ODEC;
    float* sc   = sm + O_SCT;
    float* lg   = sm + O_LG;
    float* tcx  = sm + O_TCX;
    float* tcy  = sm + O_TCY;
    float* misc = sm + O_MISC;
    float* wbuf = sm + O_WBUF;
    int* knn   = (int*)(sm + O_INT);
    int* valid = knn + 35;
    int* mask  = knn + 50;

    for (int n = tid; n < NN; n += NTH) {
        xsx[n] = p.x[(b * NN + n) * 2 + 0];
        xsy[n] = p.x[(b * NN + n) * 2 + 1];
        mask[n] = 1;
    }
    __syncthreads();
    if (tid == 0) {
        const int st = p.start[b];
        mask[st] = 0;
        misc[0] = xsx[st]; misc[1] = xsy[st];
        misc[2] = xsx[st]; misc[3] = xsy[st];
        misc[4] = 0.f;
        if (rank == 0) p.out[b * NN] = (float)st;
    }
    __syncthreads();

    for (int step = 0; step < NN - 1; step++) {
        const float lastx = misc[0], lasty = misc[1];

        float* d2 = scr;
        if (tid < NN) {
            const float dx = xsx[tid] - lastx, dy = xsy[tid] - lasty;
            d2[tid] = mask[tid] ? (dx * dx + dy * dy) : 1e9f;
        }
        __syncthreads();

        // ---- top-35: full bitonic sort of 64 packed (d2,idx) keys (jax order) ----
        if (tid < 32) {
            unsigned long long key[2];
            key[0] = (tid < NN)
                ? ((((unsigned long long)__float_as_uint(d2[tid])) << 32) | (unsigned)tid)
                : ~0ull;
            key[1] = (tid + 32 < NN)
                ? ((((unsigned long long)__float_as_uint(d2[tid + 32])) << 32) | (unsigned)(tid + 32))
                : ~0ull;
#pragma unroll
            for (int k = 2; k <= 64; k <<= 1) {
#pragma unroll
                for (int j = k >> 1; j > 0; j >>= 1) {
                    if (j == 32) {
                        const unsigned long long a = key[0] < key[1] ? key[0] : key[1];
                        const unsigned long long bmx = key[0] < key[1] ? key[1] : key[0];
                        key[0] = a; key[1] = bmx;
                    } else {
#pragma unroll
                        for (int r = 0; r < 2; r++) {
                            const int i = tid + (r << 5);
                            const unsigned long long o =
                                __shfl_xor_sync(0xffffffffu, key[r], j);
                            const bool takeMin = (((i & j) == 0) == ((i & k) == 0));
                            const bool less = key[r] < o;
                            key[r] = (takeMin == less) ? key[r] : o;
                        }
                    }
                }
            }
            knn[tid] = (int)(key[0] & 0xffffffffull);
            if (tid < 3) knn[32 + tid] = (int)(key[1] & 0xffffffffull);
        }
        __syncthreads();

        if (tid < KS) { const int n = knn[tid]; tcx[tid] = xsx[n]; tcy[tid] = xsy[n]; }
        if (tid < KA) valid[tid] = mask[knn[tid]];
        if (tid == 0) { tcx[35] = lastx; tcy[35] = lasty; tcx[36] = misc[2]; tcy[36] = misc[3]; }
        __syncthreads();

        // ---- ACTION encoder (16 tokens, 8/8 split); leading sync skippable ----
        embed<true>(h, tcx, tcy, p.aEmbW, p.aEmbB, (int)rank * 8, (int)rank * 8 + 8);
        __syncthreads();
        if (rank == 0)
            encode<SAQ, 1, 0, 0, 8, false>(h, scr, ob, wbuf, OFF_AATTN, p.aAttnB,
                                           OFF_AW1, p.aB1, OFF_AW2, p.aB2, p.aLn, prank);
        else
            encode<SAQ, 1, 4, 8, 16, false>(h, scr, ob, wbuf, OFF_AATTN, p.aAttnB,
                                            OFF_AW1, p.aB1, OFF_AW2, p.aB2, p.aLn, prank);
        // copy own SA rows to ea
        for (int i = tid + (int)rank * 1024; i < 1024 + (int)rank * 1024; i += NTH) ea[i] = h[i];
        __syncthreads();

        // ---- STATE encoder (37 tokens: 24/13 split, pairs 12/8) ----
        embed<false>(h, tcx, tcy, p.sEmbW, p.sEmbB, rank ? 24 : 0, rank ? 40 : 24);
        __syncthreads();
        if (rank == 0)
            encode<SSQ, 3, 0, 0, 24, true>(h, scr, ob, wbuf, OFF_SATTN, p.sAttnB,
                                           OFF_SW1, p.sB1, OFF_SW2, p.sB2, p.sLn, prank);
        else
            encode<SSQ, 2, 12, 24, 37, true>(h, scr, ob, wbuf, OFF_SATTN, p.sAttnB,
                                             OFF_SW1, p.sB1, OFF_SW2, p.sB2, p.sLn, prank);

        // ---- exchange encoder outputs (64-bit packed DSMEM stores) ----
        {
            const unsigned long long* eaU = reinterpret_cast<const unsigned long long*>(ea);
            const unsigned long long* hU  = reinterpret_cast<const unsigned long long*>(h);
            if (rank == 0) {
                for (int i = tid; i < 512;  i += NTH) stPeer2(eaU + i, eaU[i], prank);
                for (int i = tid; i < 1024; i += NTH) stPeer2(hU + i, hU[i], prank);
            } else {
                for (int i = tid; i < 512; i += NTH) stPeer2(eaU + 512 + i, eaU[512 + i], prank);
                for (int i = tid; i < 256; i += NTH) stPeer2(hU + 2176 + i, hU[2176 + i], prank);
            }
        }
        CLUSTER_SYNC();

        // ---- eq = [ea row15 | h row35 | h row36] — replicated ----
        if (tid < 128) {
            eq[tid]       = ea[7 * 256 + 2 * tid + 1];
            eq[128 + tid] = h[17 * 256 + 2 * tid + 1];
            eq[256 + tid] = h[18 * 256 + 2 * tid + 0];
        }
        __syncthreads();

        // ---- h_dec = emb_q @ Wq_mlp + bq_mlp (K-split) ----
        matvecK<384, false>(eq, g_wt + OFF_WQM, p.bqm, hdec, wbuf);

        // ---- K (256 cols) & V (128 cols), fused K-split directly from ea/h ----
        {
            const float* biasKV[3] = { p.bK, p.bK + 128, p.bV };
            float* outKV[3] = { Kb, Kb, Vb };
            const int obKV[3] = { 0, 128, 0 };
            const int ocKV[3] = { 256, 256, 128 };
            gemmKV<4>(ea, h, g_wt + OFF_WK, biasKV, outKV, obKV, ocKV, wbuf,
                      (int)rank * 4, prank);
        }
        CLUSTER_SYNC();   // full Kb, Vb in both CTAs

        // ---- decoder layer 0 (replicated) ----
        matvecK<128, false>(hdec, g_wt + OFF_DWQ, p.dbq, q2, wbuf);
        if (tid < 120) {
            const int head = tid & 7, kk = tid >> 3;
            float s = 0.f;
            const float* kp = Kb + kk * 256 + head * 16;
#pragma unroll
            for (int d = 0; d < 16; d++) s = fmaf(q2[head * 16 + d], kp[d], s);
            s *= 0.25f;
            sc[head * 15 + kk] = valid[kk] ? s : -1e9f;
        }
        __syncthreads();
        if (tid < 8) {
            float mx = -INFINITY;
            for (int kk = 0; kk < KA; kk++) mx = fmaxf(mx, sc[tid * 15 + kk]);
            float ssum = 0.f;
            for (int kk = 0; kk < KA; kk++) {
                const float e = __expf(sc[tid * 15 + kk] - mx);
                sc[tid * 15 + kk] = e;
                ssum += e;
            }
            const float inv = 1.0f / ssum;
            for (int kk = 0; kk < KA; kk++) sc[tid * 15 + kk] *= inv;
        }
        __syncthreads();
        if (tid < 128) {
            const int head = tid >> 4, d = tid & 15;
            float o = 0.f;
            for (int kk = 0; kk < KA; kk++)
                o = fmaf(sc[head * 15 + kk], Vb[kk * 128 + head * 16 + d], o);
            odec[tid] = o;
        }
        __syncthreads();
        matvecK<128, true>(odec, g_wt + OFF_DWO, p.dbo, hdec, wbuf);

        // ---- final pointer layer ----
        matvecK<128, false>(hdec, g_wt + OFF_DWQ + 16384, p.dbq + 128, q2, wbuf);
        if (tid < 480) {
            const int w = tid >> 5, l = tid & 31;
            const float4 qv = *reinterpret_cast<const float4*>(q2 + 4 * l);
            const float4 kv = *reinterpret_cast<const float4*>(Kb + w * 256 + 128 + 4 * l);
            float s = 0.f;
            s = fmaf(qv.x, kv.x, s);
            s = fmaf(qv.y, kv.y, s);
            s = fmaf(qv.z, kv.z, s);
            s = fmaf(qv.w, kv.w, s);
#pragma unroll
            for (int off = 16; off; off >>= 1) s += __shfl_xor_sync(0xffffffffu, s, off);
            if (l == 0) {
                s *= 0.08838834764831845f;
                s = 10.0f * tanhf(s);
                lg[w] = valid[w] ? s : -1e9f;
            }
        }
        __syncthreads();
        if (tid == 0) {
            float mx = -INFINITY; int best = 0;
            for (int kk = 0; kk < KA; kk++)
                if (lg[kk] > mx) { mx = lg[kk]; best = kk; }
            float ssum = 0.f, eb = 0.f;
            for (int kk = 0; kk < KA; kk++) {
                const float e = __expf(lg[kk] - mx);
                ssum += e;
                if (kk == best) eb = e;
            }
            misc[4] += __logf(eb / ssum);
            const int nxt = knn[best];
            mask[nxt] = 0;
            misc[0] = xsx[nxt]; misc[1] = xsy[nxt];
            if (rank == 0) p.out[b * NN + step + 1] = (float)nxt;
        }
        __syncthreads();
    }

    if (rank == 0 && tid == 0) p.out[B * NN + b] = misc[4];
    CLUSTER_SYNC();
}

extern "C" void kernel_launch(void* const* d_in, const int* in_sizes, int n_in,
                              void* d_out, int out_size)
{
    int i = 2;
    if (n_in > 2 && in_sizes[2] == 1) i = 4;

    TQJobs jb;
    const float* srcs[11] = {
        (const float*)d_in[i+2],   // aAttnW
        (const float*)d_in[i+11],  // sAttnW
        (const float*)d_in[i+4],   // aW1
        (const float*)d_in[i+13],  // sW1
        (const float*)d_in[i+6],   // aW2
        (const float*)d_in[i+15],  // sW2
        (const float*)d_in[i+18],  // WK
        (const float*)d_in[i+20],  // WV
        (const float*)d_in[i+22],  // Wqm
        (const float*)d_in[i+24],  // dWq
        (const float*)d_in[i+26],  // dWo
    };
    const int offs[11]  = {OFF_AATTN, OFF_SATTN, OFF_AW1, OFF_SW1, OFF_AW2, OFF_SW2,
                           OFF_WK, OFF_WV, OFF_WQM, OFF_DWQ, OFF_DWO};
    const int Rs[11]    = {128, 128, 128, 128, 512, 512, 256, 256, 384, 128, 128};
    const int Cs[11]    = {128, 128, 512, 512, 128, 128, 256, 256, 128, 128, 128};
    const int nms[11]   = {8, 8, 2, 2, 2, 2, 1, 1, 1, 2, 2};
    for (int s = 0; s < 11; s++) {
        jb.src[s] = srcs[s]; jb.dstOff[s] = offs[s];
        jb.R[s] = Rs[s]; jb.C[s] = Cs[s]; jb.nmat[s] = nms[s];
    }
    tq_all<<<128, 256>>>(jb);

    Params p;
    p.x = (const float*)d_in[0];
    p.start = (const int*)d_in[1];
    p.aEmbW = (const float*)d_in[i+0];  p.aEmbB = (const float*)d_in[i+1];
    p.aAttnB = (const float*)d_in[i+3];
    p.aB1 = (const float*)d_in[i+5];    p.aB2 = (const float*)d_in[i+7];
    p.aLn = (const float*)d_in[i+8];
    p.sEmbW = (const float*)d_in[i+9];  p.sEmbB = (const float*)d_in[i+10];
    p.sAttnB = (const float*)d_in[i+12];
    p.sB1 = (const float*)d_in[i+14];   p.sB2 = (const float*)d_in[i+16];
    p.sLn = (const float*)d_in[i+17];
    p.bK  = (const float*)d_in[i+19];
    p.bV  = (const float*)d_in[i+21];
    p.bqm = (const float*)d_in[i+23];
    p.dbq = (const float*)d_in[i+25];
    p.dbo = (const float*)d_in[i+27];
    p.out = (float*)d_out;

    cudaFuncSetAttribute(tsp_kernel, cudaFuncAttributeMaxDynamicSharedMemorySize, SMEM_BYTES);

    const int B = in_sizes[1];
    tsp_kernel<<<2 * B, NTH, SMEM_BYTES>>>(p);
}